// round 8
// baseline (speedup 1.0000x reference)
#include <cuda_runtime.h>
#include <cstdint>

#define NP 100000
#define NA 50000
#define H  128
#define EC_MAX 1000000
#define EW_MAX 320000

// ---------------- device scratch ----------------
__device__ float g_acc_c[(size_t)NP * H];
__device__ float g_acc_w[(size_t)NP * H];
__device__ float g_acc_r[(size_t)NA * H];
__device__ float g_Oc[(size_t)NP * H];
__device__ float g_Ow[(size_t)NP * H];
__device__ float g_Or[(size_t)NA * H];
__device__ float g_xp[(size_t)NP * H];
__device__ float g_xa[(size_t)NA * H];
__device__ float g_Bf[6][65536];                // fragment-major weights (hi+lo)
// CSR
__device__ int g_cnt_c[NP], g_cnt_w[NP], g_cnt_r[NA];
__device__ int g_rp_c[NP], g_rp_w[NP], g_rp_r[NA];
__device__ int g_cur_c[NP], g_cur_w[NP], g_cur_r[NA];
__device__ int g_col_c[EC_MAX], g_col_w[EW_MAX], g_col_r[EW_MAX];
__device__ int g_total[3];

// ---------------- helpers ----------------
__device__ __forceinline__ uint32_t f2tf_u(float f) {
    uint32_t r;
    asm("cvt.rna.tf32.f32 %0, %1;" : "=r"(r) : "f"(f));
    return r;
}
__device__ __forceinline__ float f2tf_f(float f) { return __uint_as_float(f2tf_u(f)); }

// ---------------- CSR build ----------------
__global__ void counti_kernel(const int* __restrict__ dst, int* __restrict__ cnt, int nE) {
    int e = blockIdx.x * blockDim.x + threadIdx.x;
    if (e < nE) atomicAdd(&cnt[dst[e]], 1);
}

__global__ void assign_kernel(const int* __restrict__ cnt, int* __restrict__ rp,
                              int* __restrict__ cur, int* __restrict__ total, int n) {
    int i = blockIdx.x * blockDim.x + threadIdx.x;
    int lane = threadIdx.x & 31;
    int v = (i < n) ? cnt[i] : 0;
    int incl = v;
#pragma unroll
    for (int o = 1; o < 32; o <<= 1) {
        int t = __shfl_up_sync(0xffffffffu, incl, o);
        if (lane >= o) incl += t;
    }
    int wsum = __shfl_sync(0xffffffffu, incl, 31);
    int base = 0;
    if (lane == 31) base = atomicAdd(total, wsum);
    base = __shfl_sync(0xffffffffu, base, 31);
    int off = base + incl - v;
    if (i < n) { rp[i] = off; cur[i] = off; }
}

__global__ void fill_kernel(const int* __restrict__ src, const int* __restrict__ dst,
                            int* __restrict__ cur, int* __restrict__ col, int nE) {
    int e = blockIdx.x * blockDim.x + threadIdx.x;
    if (e < nE) {
        int d = dst[e];
        int p = atomicAdd(&cur[d], 1);
        col[p] = src[e];
    }
}

// ---------------- gather-mean aggregation: warp per dst node ----------------
__global__ void aggregate_kernel(const float* __restrict__ x, const int* __restrict__ rp,
                                 const int* __restrict__ cnt, const int* __restrict__ col,
                                 float* __restrict__ acc, int n) {
    int gw   = (blockIdx.x * blockDim.x + threadIdx.x) >> 5;
    int lane = threadIdx.x & 31;
    if (gw >= n) return;
    const int beg = __ldg(&rp[gw]);
    const int deg = __ldg(&cnt[gw]);
    const int end = beg + deg;
    float4 s = make_float4(0.f, 0.f, 0.f, 0.f);
    for (int b = beg; b < end; b += 32) {
        int nb = min(32, end - b);
        int my = (b + lane < end) ? __ldg(&col[b + lane]) : 0;
        for (int j = 0; j < nb; j++) {
            int sn = __shfl_sync(0xffffffffu, my, j);
            float4 v = *(const float4*)(x + (size_t)sn * H + lane * 4);
            s.x += v.x; s.y += v.y; s.z += v.z; s.w += v.w;
        }
    }
    float inv = 1.0f / fmaxf((float)deg, 1.0f);
    s.x *= inv; s.y *= inv; s.z *= inv; s.w *= inv;
    *(float4*)(acc + (size_t)gw * H + lane * 4) = s;
}

// ---------------- fragment-major weight prep ----------------
// Block index blk = g*4 + wn*2 + mat (g = K-step of 8), each block 512 floats.
// offset within block = j*128 + (cq*8+rq)*4 + e; nt = 2j+(e>>1), b = e&1.
// Element = W[k][col], k = g*8+cq+b*4, col = wn*64+nt*8+rq; hi or lo split.
__global__ void prep_bf(const float* __restrict__ Wl, const float* __restrict__ Wr,
                        float* __restrict__ Bf) {
    int i = blockIdx.x * blockDim.x + threadIdx.x;   // 65536
    if (i >= 65536) return;
    int blk = i >> 9;
    int mat = blk & 1, wn = (blk >> 1) & 1, g = blk >> 2;
    int o = i & 511;
    int j = o >> 7;
    int r7 = (o >> 2) & 31;
    int cq = r7 >> 3, rq = r7 & 7;
    int e = o & 3;
    int nt = 2 * j + (e >> 1);
    int b = e & 1;
    int k = g * 8 + cq + b * 4;
    int col = wn * 64 + nt * 8 + rq;
    float w = (k < 128) ? Wl[k * 128 + col] : Wr[(k - 128) * 128 + col];
    float h = f2tf_f(w);
    Bf[i] = mat ? f2tf_f(w - h) : h;
}

// ---------------- tf32 mma.sync GEMM (R5 structure, fragment-major B) ----------------
// dynamic smem (floats): bs[128] | As[128*36] | Bsm[8192]
#define SMF_AS 128
#define SMF_B  (SMF_AS + 128 * 36)
#define SM_GEMM_BYTES ((SMF_B + 8192) * 4)

__global__ void __launch_bounds__(256, 2) sage_gemm_tc(
    const float* __restrict__ acc, const float* __restrict__ xdst,
    const float* __restrict__ Bf, const float* __restrict__ bias,
    float* __restrict__ O, int n)
{
    extern __shared__ float sm[];
    float* bs  = sm;
    float* As  = sm + SMF_AS;
    float* Bsm = sm + SMF_B;

    const int tid  = threadIdx.x;
    const int lane = tid & 31;
    const int wid  = tid >> 5;
    const int wm   = wid & 3;
    const int wn   = wid >> 2;
    const int row0 = blockIdx.x * 128;
    const int rq   = lane >> 2;
    const int cq   = lane & 3;

    if (tid < 128) bs[tid] = __ldg(&bias[tid]);
    __syncthreads();

    float c[2][8][4];
#pragma unroll
    for (int mt = 0; mt < 2; mt++)
#pragma unroll
        for (int nt = 0; nt < 8; nt++) {
            float b0 = bs[wn * 64 + nt * 8 + cq * 2];
            float b1 = bs[wn * 64 + nt * 8 + cq * 2 + 1];
            c[mt][nt][0] = b0; c[mt][nt][1] = b1;
            c[mt][nt][2] = b0; c[mt][nt][3] = b1;
        }

    const int tb = (cq * 8 + rq) * 4;   // fragment lane offset within 512-float block

    for (int ch = 0; ch < 8; ch++) {
        const int kc = ch * 32;
        __syncthreads();
        // ---- A tile [128 m][32 k] -> tf32, stride 36 ----
#pragma unroll
        for (int l = 0; l < 4; l++) {
            int idx = tid + l * 256;
            int r   = idx >> 3;
            int klv = (idx & 7) << 2;
            int rg  = row0 + r;
            float4 v = make_float4(0.f, 0.f, 0.f, 0.f);
            if (rg < n) {
                int kg = kc + klv;
                v = (kg < 128)
                    ? *(const float4*)(acc + (size_t)rg * H + kg)
                    : *(const float4*)(xdst + (size_t)rg * H + (kg - 128));
            }
            float* p = As + r * 36 + klv;
            p[0] = f2tf_f(v.x); p[1] = f2tf_f(v.y); p[2] = f2tf_f(v.z); p[3] = f2tf_f(v.w);
        }
        // ---- B slice: contiguous 8192 floats of fragment-major table ----
        {
            const float4* src = (const float4*)(Bf + ch * 8192);
#pragma unroll
            for (int l = 0; l < 8; l++) {
                int idx = tid + l * 256;
                ((float4*)Bsm)[idx] = __ldg(&src[idx]);
            }
        }
        __syncthreads();

        // ---- compute: 4 ksteps of 8 ----
#pragma unroll
        for (int ks = 0; ks < 4; ks++) {
            const int k0 = ks * 8;
            uint32_t au[2][4];
#pragma unroll
            for (int mt = 0; mt < 2; mt++) {
                const float* ap = As + (wm * 32 + mt * 16 + rq) * 36 + k0 + cq;
                au[mt][0] = __float_as_uint(ap[0]);
                au[mt][1] = __float_as_uint(ap[8 * 36]);
                au[mt][2] = __float_as_uint(ap[4]);
                au[mt][3] = __float_as_uint(ap[8 * 36 + 4]);
            }
#pragma unroll
            for (int mat = 0; mat < 2; mat++) {
                const float* bp = Bsm + ((ks * 4 + wn * 2 + mat) << 9) + tb;
#pragma unroll
                for (int j = 0; j < 4; j++) {
                    float4 f = *(const float4*)(bp + j * 128);
                    uint32_t b0a = __float_as_uint(f.x), b1a = __float_as_uint(f.y);
                    uint32_t b0b = __float_as_uint(f.z), b1b = __float_as_uint(f.w);
                    const int nt0 = 2 * j, nt1 = 2 * j + 1;
#pragma unroll
                    for (int mt = 0; mt < 2; mt++) {
                        asm volatile(
                            "mma.sync.aligned.m16n8k8.row.col.f32.tf32.tf32.f32 "
                            "{%0, %1, %2, %3}, {%4, %5, %6, %7}, {%8, %9}, {%0, %1, %2, %3};"
                            : "+f"(c[mt][nt0][0]), "+f"(c[mt][nt0][1]),
                              "+f"(c[mt][nt0][2]), "+f"(c[mt][nt0][3])
                            : "r"(au[mt][0]), "r"(au[mt][1]), "r"(au[mt][2]), "r"(au[mt][3]),
                              "r"(b0a), "r"(b1a));
                        asm volatile(
                            "mma.sync.aligned.m16n8k8.row.col.f32.tf32.tf32.f32 "
                            "{%0, %1, %2, %3}, {%4, %5, %6, %7}, {%8, %9}, {%0, %1, %2, %3};"
                            : "+f"(c[mt][nt1][0]), "+f"(c[mt][nt1][1]),
                              "+f"(c[mt][nt1][2]), "+f"(c[mt][nt1][3])
                            : "r"(au[mt][0]), "r"(au[mt][1]), "r"(au[mt][2]), "r"(au[mt][3]),
                              "r"(b0b), "r"(b1b));
                    }
                }
            }
        }
    }

    // ---- plain biased store (R5 epilogue) ----
#pragma unroll
    for (int mt = 0; mt < 2; mt++) {
        int r = row0 + wm * 32 + mt * 16 + rq;
#pragma unroll
        for (int nt = 0; nt < 8; nt++) {
            int col = wn * 64 + nt * 8 + cq * 2;
            if (r < n)
                *(float2*)(O + (size_t)r * H + col) = make_float2(c[mt][nt][0], c[mt][nt][1]);
            if (r + 8 < n)
                *(float2*)(O + (size_t)(r + 8) * H + col) = make_float2(c[mt][nt][2], c[mt][nt][3]);
        }
    }
}

// ---------------- finalize ----------------
__global__ void finalize_paper(const float* __restrict__ Oc, const float* __restrict__ Ow,
                               float* __restrict__ out) {
    int gw   = (blockIdx.x * blockDim.x + threadIdx.x) >> 5;
    int lane = threadIdx.x & 31;
    if (gw >= NP) return;
    float4 cc = *(const float4*)(Oc + (size_t)gw * H + lane * 4);
    float4 w = *(const float4*)(Ow + (size_t)gw * H + lane * 4);
    float sc = cc.x*cc.x + cc.y*cc.y + cc.z*cc.z + cc.w*cc.w;
    float sw = w.x*w.x + w.y*w.y + w.z*w.z + w.w*w.w;
#pragma unroll
    for (int o = 16; o > 0; o >>= 1) {
        sc += __shfl_xor_sync(0xffffffffu, sc, o);
        sw += __shfl_xor_sync(0xffffffffu, sw, o);
    }
    float ic = 0.5f / fmaxf(sqrtf(sc), 1e-12f);
    float iw = 0.5f / fmaxf(sqrtf(sw), 1e-12f);
    float4 r;
    r.x = fmaxf(cc.x * ic + w.x * iw, 0.f);
    r.y = fmaxf(cc.y * ic + w.y * iw, 0.f);
    r.z = fmaxf(cc.z * ic + w.z * iw, 0.f);
    r.w = fmaxf(cc.w * ic + w.w * iw, 0.f);
    *(float4*)(out + (size_t)gw * H + lane * 4) = r;
}
__global__ void finalize_author(const float* __restrict__ Or, float* __restrict__ out) {
    int gw   = (blockIdx.x * blockDim.x + threadIdx.x) >> 5;
    int lane = threadIdx.x & 31;
    if (gw >= NA) return;
    float4 cc = *(const float4*)(Or + (size_t)gw * H + lane * 4);
    float sc = cc.x*cc.x + cc.y*cc.y + cc.z*cc.z + cc.w*cc.w;
#pragma unroll
    for (int o = 16; o > 0; o >>= 1) sc += __shfl_xor_sync(0xffffffffu, sc, o);
    float ic = 1.0f / fmaxf(sqrtf(sc), 1e-12f);
    float4 r;
    r.x = fmaxf(cc.x * ic, 0.f);
    r.y = fmaxf(cc.y * ic, 0.f);
    r.z = fmaxf(cc.z * ic, 0.f);
    r.w = fmaxf(cc.w * ic, 0.f);
    *(float4*)(out + (size_t)gw * H + lane * 4) = r;
}

// ---------------- host launcher ----------------
extern "C" void kernel_launch(void* const* d_in, const int* in_sizes, int n_in,
                              void* d_out, int out_size) {
    const float* x_paper  = (const float*)d_in[0];
    const float* x_author = (const float*)d_in[1];
    const int* cs = (const int*)d_in[2];
    const int* cd = (const int*)d_in[3];
    const int* ws = (const int*)d_in[4];
    const int* wd = (const int*)d_in[5];
    const int* rs = (const int*)d_in[6];
    const int* rd = (const int*)d_in[7];
    const int EC = in_sizes[2];
    const int EW = in_sizes[4];
    const float* W[18];
    for (int i = 0; i < 18; i++) W[i] = (const float*)d_in[8 + i];

    float *acc_c, *acc_w, *acc_r, *Oc, *Ow, *Or, *xp, *xa, *BfB;
    int *cnt_c, *cnt_w, *cnt_r, *rp_c, *rp_w, *rp_r, *cur_c, *cur_w, *cur_r;
    int *col_c, *col_w, *col_r, *total;
    cudaGetSymbolAddress((void**)&acc_c, g_acc_c);
    cudaGetSymbolAddress((void**)&acc_w, g_acc_w);
    cudaGetSymbolAddress((void**)&acc_r, g_acc_r);
    cudaGetSymbolAddress((void**)&Oc, g_Oc);
    cudaGetSymbolAddress((void**)&Ow, g_Ow);
    cudaGetSymbolAddress((void**)&Or, g_Or);
    cudaGetSymbolAddress((void**)&xp, g_xp);
    cudaGetSymbolAddress((void**)&xa, g_xa);
    cudaGetSymbolAddress((void**)&BfB, g_Bf);
    cudaGetSymbolAddress((void**)&cnt_c, g_cnt_c);
    cudaGetSymbolAddress((void**)&cnt_w, g_cnt_w);
    cudaGetSymbolAddress((void**)&cnt_r, g_cnt_r);
    cudaGetSymbolAddress((void**)&rp_c, g_rp_c);
    cudaGetSymbolAddress((void**)&rp_w, g_rp_w);
    cudaGetSymbolAddress((void**)&rp_r, g_rp_r);
    cudaGetSymbolAddress((void**)&cur_c, g_cur_c);
    cudaGetSymbolAddress((void**)&cur_w, g_cur_w);
    cudaGetSymbolAddress((void**)&cur_r, g_cur_r);
    cudaGetSymbolAddress((void**)&col_c, g_col_c);
    cudaGetSymbolAddress((void**)&col_w, g_col_w);
    cudaGetSymbolAddress((void**)&col_r, g_col_r);
    cudaGetSymbolAddress((void**)&total, g_total);

    cudaFuncSetAttribute(sage_gemm_tc, cudaFuncAttributeMaxDynamicSharedMemorySize, SM_GEMM_BYTES);

    // ---- CSR build ----
    cudaMemsetAsync(cnt_c, 0, NP * sizeof(int));
    cudaMemsetAsync(cnt_w, 0, NP * sizeof(int));
    cudaMemsetAsync(cnt_r, 0, NA * sizeof(int));
    cudaMemsetAsync(total, 0, 3 * sizeof(int));
    counti_kernel<<<(EC + 255) / 256, 256>>>(cd, cnt_c, EC);
    counti_kernel<<<(EW + 255) / 256, 256>>>(wd, cnt_w, EW);
    counti_kernel<<<(EW + 255) / 256, 256>>>(rd, cnt_r, EW);
    assign_kernel<<<(NP + 255) / 256, 256>>>(cnt_c, rp_c, cur_c, total + 0, NP);
    assign_kernel<<<(NP + 255) / 256, 256>>>(cnt_w, rp_w, cur_w, total + 1, NP);
    assign_kernel<<<(NA + 255) / 256, 256>>>(cnt_r, rp_r, cur_r, total + 2, NA);
    fill_kernel<<<(EC + 255) / 256, 256>>>(cs, cd, cur_c, col_c, EC);
    fill_kernel<<<(EW + 255) / 256, 256>>>(ws, wd, cur_w, col_w, EW);
    fill_kernel<<<(EW + 255) / 256, 256>>>(rs, rd, cur_r, col_r, EW);

    // ---- fragment-major split weights ----
    for (int l = 0; l < 2; l++)
        for (int t = 0; t < 3; t++) {
            const float* Wl = W[l * 9 + t * 3 + 0];
            const float* Wr = W[l * 9 + t * 3 + 2];
            prep_bf<<<256, 256>>>(Wl, Wr, BfB + (l * 3 + t) * 65536);
        }

    const float* xpl = x_paper;
    const float* xal = x_author;
    for (int l = 0; l < 2; l++) {
        aggregate_kernel<<<(NP * 32 + 255) / 256, 256>>>(xpl, rp_c, cnt_c, col_c, acc_c, NP);
        aggregate_kernel<<<(NP * 32 + 255) / 256, 256>>>(xal, rp_w, cnt_w, col_w, acc_w, NP);
        aggregate_kernel<<<(NA * 32 + 255) / 256, 256>>>(xpl, rp_r, cnt_r, col_r, acc_r, NA);

        const float* Bfc = BfB + (l * 3 + 0) * 65536;
        const float* Bfw = BfB + (l * 3 + 1) * 65536;
        const float* Bfr = BfB + (l * 3 + 2) * 65536;

        sage_gemm_tc<<<(NP + 127) / 128, 256, SM_GEMM_BYTES>>>(
            acc_c, xpl, Bfc, W[l * 9 + 1], Oc, NP);
        sage_gemm_tc<<<(NP + 127) / 128, 256, SM_GEMM_BYTES>>>(
            acc_w, xpl, Bfw, W[l * 9 + 4], Ow, NP);
        sage_gemm_tc<<<(NA + 127) / 128, 256, SM_GEMM_BYTES>>>(
            acc_r, xal, Bfr, W[l * 9 + 7], Or, NA);

        float* po = (l == 1) ? (float*)d_out : xp;
        float* ao = (l == 1) ? ((float*)d_out + (size_t)NP * H) : xa;
        finalize_paper<<<(NP * 32 + 255) / 256, 256>>>(Oc, Ow, po);
        finalize_author<<<(NA * 32 + 255) / 256, 256>>>(Or, ao);

        xpl = xp;
        xal = xa;
    }
    (void)n_in; (void)out_size; (void)x_author;
}

// round 9
// speedup vs baseline: 1.2936x; 1.2936x over previous
#include <cuda_runtime.h>
#include <cstdint>

#define NP 100000
#define NA 50000
#define H  128
#define EC_MAX 1000000
#define EW_MAX 320000
#define GC 782
#define GW 782
#define GR 391

// ---------------- device scratch ----------------
__device__ float g_acc_c[(size_t)NP * H];
__device__ float g_acc_w[(size_t)NP * H];
__device__ float g_acc_r[(size_t)NA * H];
__device__ float g_Oc[(size_t)NP * H];
__device__ float g_Ow[(size_t)NP * H];
__device__ float g_Or[(size_t)NA * H];
__device__ float g_xp[(size_t)NP * H];
__device__ float g_xa[(size_t)NA * H];
__device__ float g_Whi[6][256 * 128];   // [k][n] tf32(hi)
__device__ float g_Wlo[6][256 * 128];   // [k][n] tf32(lo)
// CSR
__device__ int g_cnt_c[NP], g_cnt_w[NP], g_cnt_r[NA];
__device__ int g_rp_c[NP], g_rp_w[NP], g_rp_r[NA];
__device__ int g_cur_c[NP], g_cur_w[NP], g_cur_r[NA];
__device__ int g_col_c[EC_MAX], g_col_w[EW_MAX], g_col_r[EW_MAX];
__device__ int g_total[3];

// ---------------- helpers ----------------
__device__ __forceinline__ uint32_t f2tf_u(float f) {
    uint32_t r;
    asm("cvt.rna.tf32.f32 %0, %1;" : "=r"(r) : "f"(f));
    return r;
}
__device__ __forceinline__ float f2tf_f(float f) { return __uint_as_float(f2tf_u(f)); }

// ---------------- merged CSR build ----------------
__global__ void counti_all(const int* __restrict__ cd, const int* __restrict__ wd,
                           const int* __restrict__ rd, int* __restrict__ cnt_c,
                           int* __restrict__ cnt_w, int* __restrict__ cnt_r,
                           int EC, int EW) {
    int e = blockIdx.x * blockDim.x + threadIdx.x;
    if (e < EC)               atomicAdd(&cnt_c[cd[e]], 1);
    else if (e < EC + EW)     atomicAdd(&cnt_w[wd[e - EC]], 1);
    else if (e < EC + 2 * EW) atomicAdd(&cnt_r[rd[e - EC - EW]], 1);
}

// merged segment-offset assignment (warp-aggregated atomic; segment
// boundaries NP and 2*NP are multiples of 32 so warps never straddle)
__global__ void assign_all(const int* __restrict__ cnt_c, const int* __restrict__ cnt_w,
                           const int* __restrict__ cnt_r,
                           int* __restrict__ rp_c, int* __restrict__ rp_w, int* __restrict__ rp_r,
                           int* __restrict__ cur_c, int* __restrict__ cur_w, int* __restrict__ cur_r,
                           int* __restrict__ total) {
    int i = blockIdx.x * blockDim.x + threadIdx.x;
    int lane = threadIdx.x & 31;
    const int NTOT = 2 * NP + NA;
    int seg = (i >= NP) + (i >= 2 * NP);
    int li = i - (seg == 1 ? NP : (seg == 2 ? 2 * NP : 0));
    const int* cnt = (seg == 0) ? cnt_c : (seg == 1) ? cnt_w : cnt_r;
    int v = (i < NTOT) ? cnt[li] : 0;
    int incl = v;
#pragma unroll
    for (int o = 1; o < 32; o <<= 1) {
        int t = __shfl_up_sync(0xffffffffu, incl, o);
        if (lane >= o) incl += t;
    }
    int wsum = __shfl_sync(0xffffffffu, incl, 31);
    int base = 0;
    if (lane == 31) base = atomicAdd(&total[seg], wsum);
    base = __shfl_sync(0xffffffffu, base, 31);
    int off = base + incl - v;
    if (i < NTOT) {
        int* rp  = (seg == 0) ? rp_c  : (seg == 1) ? rp_w  : rp_r;
        int* cur = (seg == 0) ? cur_c : (seg == 1) ? cur_w : cur_r;
        rp[li] = off; cur[li] = off;
    }
}

__global__ void fill_all(const int* __restrict__ cs, const int* __restrict__ cd,
                         const int* __restrict__ ws, const int* __restrict__ wd,
                         const int* __restrict__ rs, const int* __restrict__ rd,
                         int* __restrict__ cur_c, int* __restrict__ cur_w, int* __restrict__ cur_r,
                         int* __restrict__ col_c, int* __restrict__ col_w, int* __restrict__ col_r,
                         int EC, int EW) {
    int e = blockIdx.x * blockDim.x + threadIdx.x;
    const int* src; const int* dst; int* cur; int* col; int le;
    if (e < EC)               { src = cs; dst = cd; cur = cur_c; col = col_c; le = e; }
    else if (e < EC + EW)     { src = ws; dst = wd; cur = cur_w; col = col_w; le = e - EC; }
    else if (e < EC + 2 * EW) { src = rs; dst = rd; cur = cur_r; col = col_r; le = e - EC - EW; }
    else return;
    int d = dst[le];
    int p = atomicAdd(&cur[d], 1);
    col[p] = src[le];
}

// ---------------- merged gather-mean aggregation: warp per dst node ----------------
__global__ void aggregate_all(const float* __restrict__ xp_, const float* __restrict__ xa_,
                              const int* __restrict__ rp_c, const int* __restrict__ rp_w,
                              const int* __restrict__ rp_r,
                              const int* __restrict__ cnt_c, const int* __restrict__ cnt_w,
                              const int* __restrict__ cnt_r,
                              const int* __restrict__ col_c, const int* __restrict__ col_w,
                              const int* __restrict__ col_r,
                              float* __restrict__ acc_c, float* __restrict__ acc_w,
                              float* __restrict__ acc_r) {
    int gw   = (blockIdx.x * blockDim.x + threadIdx.x) >> 5;
    int lane = threadIdx.x & 31;
    if (gw >= 2 * NP + NA) return;
    int seg = (gw >= NP) + (gw >= 2 * NP);
    int node = gw - (seg == 1 ? NP : (seg == 2 ? 2 * NP : 0));
    const float* x  = (seg == 1) ? xa_ : xp_;
    const int* rp   = (seg == 0) ? rp_c  : (seg == 1) ? rp_w  : rp_r;
    const int* cnt  = (seg == 0) ? cnt_c : (seg == 1) ? cnt_w : cnt_r;
    const int* col  = (seg == 0) ? col_c : (seg == 1) ? col_w : col_r;
    float* acc      = (seg == 0) ? acc_c : (seg == 1) ? acc_w : acc_r;

    const int beg = __ldg(&rp[node]);
    const int deg = __ldg(&cnt[node]);
    const int end = beg + deg;
    float4 s = make_float4(0.f, 0.f, 0.f, 0.f);
    for (int b = beg; b < end; b += 32) {
        int nb = min(32, end - b);
        int my = (b + lane < end) ? __ldg(&col[b + lane]) : 0;
        for (int j = 0; j < nb; j++) {
            int sn = __shfl_sync(0xffffffffu, my, j);
            float4 v = *(const float4*)(x + (size_t)sn * H + lane * 4);
            s.x += v.x; s.y += v.y; s.z += v.z; s.w += v.w;
        }
    }
    float inv = 1.0f / fmaxf((float)deg, 1.0f);
    s.x *= inv; s.y *= inv; s.z *= inv; s.w *= inv;
    *(float4*)(acc + (size_t)node * H + lane * 4) = s;
}

// ---------------- merged weight split (6 matrices) ----------------
struct PrepArgs { const float* Wl[6]; const float* Wr[6]; };
__global__ void prep_all(PrepArgs pa, float* __restrict__ hi, float* __restrict__ lo) {
    int i = blockIdx.x * blockDim.x + threadIdx.x;   // 6*32768
    if (i >= 6 * 32768) return;
    int t = i >> 15;
    int o = i & 32767;
    int k = o >> 7, nn = o & 127;
    float w = (k < 128) ? pa.Wl[t][k * 128 + nn] : pa.Wr[t][(k - 128) * 128 + nn];
    float h = f2tf_f(w);
    hi[i] = h;
    lo[i] = f2tf_f(w - h);
}

// ---------------- merged tf32 mma.sync GEMM (R5 inner loop, untouched) ----------------
#define AS_STRIDE 36
#define BS_STRIDE 132
#define SMF_A  128
#define SMF_BH (SMF_A + 128 * AS_STRIDE)
#define SMF_BL (SMF_BH + 32 * BS_STRIDE)
#define SM_GEMM_BYTES ((SMF_BL + 32 * BS_STRIDE) * 4)   // 52736

__global__ void __launch_bounds__(256, 2) sage_gemm_all(
    const float* __restrict__ accC, const float* __restrict__ accW,
    const float* __restrict__ accR,
    const float* __restrict__ xp_, const float* __restrict__ xa_,
    const float* __restrict__ WhiL, const float* __restrict__ WloL,
    const float* __restrict__ bC, const float* __restrict__ bW,
    const float* __restrict__ bR,
    float* __restrict__ OC, float* __restrict__ OW, float* __restrict__ OR_)
{
    extern __shared__ float sm[];
    float* bs = sm;
    float* As = sm + SMF_A;
    float* Bh = sm + SMF_BH;
    float* Bl = sm + SMF_BL;

    const int b = blockIdx.x;
    const int seg = (b >= GC) + (b >= GC + GW);
    const int bloc = b - (seg == 1 ? GC : (seg == 2 ? GC + GW : 0));
    const float* acc  = (seg == 0) ? accC : (seg == 1) ? accW : accR;
    const float* xdst = (seg == 2) ? xa_ : xp_;
    const float* Whi  = WhiL + seg * 32768;
    const float* Wlo  = WloL + seg * 32768;
    const float* bias = (seg == 0) ? bC : (seg == 1) ? bW : bR;
    float* O          = (seg == 0) ? OC : (seg == 1) ? OW : OR_;
    const int n       = (seg == 2) ? NA : NP;

    const int tid  = threadIdx.x;
    const int lane = tid & 31;
    const int wid  = tid >> 5;
    const int wm   = wid & 3;
    const int wn   = wid >> 2;
    const int row0 = bloc * 128;
    const int rq   = lane >> 2;
    const int cq   = lane & 3;

    if (tid < 128) bs[tid] = __ldg(&bias[tid]);
    __syncthreads();

    float c[2][8][4];
#pragma unroll
    for (int mt = 0; mt < 2; mt++)
#pragma unroll
        for (int nt = 0; nt < 8; nt++) {
            float b0 = bs[wn * 64 + nt * 8 + cq * 2];
            float b1 = bs[wn * 64 + nt * 8 + cq * 2 + 1];
            c[mt][nt][0] = b0; c[mt][nt][1] = b1;
            c[mt][nt][2] = b0; c[mt][nt][3] = b1;
        }

    for (int ch = 0; ch < 8; ch++) {
        const int kc = ch * 32;
        __syncthreads();
        // ---- A tile [128 m][32 k] -> tf32, stride 36 ----
#pragma unroll
        for (int l = 0; l < 4; l++) {
            int idx = tid + l * 256;
            int r   = idx >> 3;
            int klv = (idx & 7) << 2;
            int rg  = row0 + r;
            float4 v = make_float4(0.f, 0.f, 0.f, 0.f);
            if (rg < n) {
                int kg = kc + klv;
                v = (kg < 128)
                    ? *(const float4*)(acc + (size_t)rg * H + kg)
                    : *(const float4*)(xdst + (size_t)rg * H + (kg - 128));
            }
            float* p = As + r * AS_STRIDE + klv;
            p[0] = f2tf_f(v.x); p[1] = f2tf_f(v.y); p[2] = f2tf_f(v.z); p[3] = f2tf_f(v.w);
        }
        // ---- B tiles: Bh/Bl [32 k][128 n], pad 132 ----
#pragma unroll
        for (int l = 0; l < 8; l++) {
            int idx = tid + l * 256;
            int mat = idx >> 10;
            int rem = idx & 1023;
            int k   = rem >> 5;
            int nv  = (rem & 31) << 2;
            const float* src = (mat ? Wlo : Whi) + (size_t)(kc + k) * 128 + nv;
            float4 v = *(const float4*)src;
            float* dstp = (mat ? Bl : Bh) + k * BS_STRIDE + nv;
            *(float4*)dstp = v;
        }
        __syncthreads();

        // ---- compute: 4 ksteps of 8 ----
#pragma unroll
        for (int ks = 0; ks < 4; ks++) {
            const int k0 = ks * 8;
            uint32_t au[2][4];
#pragma unroll
            for (int mt = 0; mt < 2; mt++) {
                const float* ap = As + (wm * 32 + mt * 16 + rq) * AS_STRIDE + k0 + cq;
                au[mt][0] = __float_as_uint(ap[0]);
                au[mt][1] = __float_as_uint(ap[8 * AS_STRIDE]);
                au[mt][2] = __float_as_uint(ap[4]);
                au[mt][3] = __float_as_uint(ap[8 * AS_STRIDE + 4]);
            }
#pragma unroll
            for (int mat = 0; mat < 2; mat++) {
                const float* B = mat ? Bl : Bh;
#pragma unroll
                for (int nt = 0; nt < 8; nt++) {
                    const float* bp = B + (k0 + cq) * BS_STRIDE + wn * 64 + nt * 8 + rq;
                    uint32_t b0 = __float_as_uint(bp[0]);
                    uint32_t b1 = __float_as_uint(bp[4 * BS_STRIDE]);
#pragma unroll
                    for (int mt = 0; mt < 2; mt++) {
                        asm volatile(
                            "mma.sync.aligned.m16n8k8.row.col.f32.tf32.tf32.f32 "
                            "{%0, %1, %2, %3}, {%4, %5, %6, %7}, {%8, %9}, {%0, %1, %2, %3};"
                            : "+f"(c[mt][nt][0]), "+f"(c[mt][nt][1]),
                              "+f"(c[mt][nt][2]), "+f"(c[mt][nt][3])
                            : "r"(au[mt][0]), "r"(au[mt][1]), "r"(au[mt][2]), "r"(au[mt][3]),
                              "r"(b0), "r"(b1));
                    }
                }
            }
        }
    }

    // ---- plain biased store ----
#pragma unroll
    for (int mt = 0; mt < 2; mt++) {
        int r = row0 + wm * 32 + mt * 16 + rq;
#pragma unroll
        for (int nt = 0; nt < 8; nt++) {
            int col = wn * 64 + nt * 8 + cq * 2;
            if (r < n)
                *(float2*)(O + (size_t)r * H + col) = make_float2(c[mt][nt][0], c[mt][nt][1]);
            if (r + 8 < n)
                *(float2*)(O + (size_t)(r + 8) * H + col) = make_float2(c[mt][nt][2], c[mt][nt][3]);
        }
    }
}

// ---------------- merged finalize (paper + author) ----------------
__global__ void finalize_all(const float* __restrict__ Oc, const float* __restrict__ Ow,
                             const float* __restrict__ Or_,
                             float* __restrict__ pout, float* __restrict__ aout) {
    int gw   = (blockIdx.x * blockDim.x + threadIdx.x) >> 5;
    int lane = threadIdx.x & 31;
    if (gw >= NP + NA) return;
    if (gw < NP) {
        float4 cc = *(const float4*)(Oc + (size_t)gw * H + lane * 4);
        float4 w = *(const float4*)(Ow + (size_t)gw * H + lane * 4);
        float sc = cc.x*cc.x + cc.y*cc.y + cc.z*cc.z + cc.w*cc.w;
        float sw = w.x*w.x + w.y*w.y + w.z*w.z + w.w*w.w;
#pragma unroll
        for (int o = 16; o > 0; o >>= 1) {
            sc += __shfl_xor_sync(0xffffffffu, sc, o);
            sw += __shfl_xor_sync(0xffffffffu, sw, o);
        }
        float ic = 0.5f / fmaxf(sqrtf(sc), 1e-12f);
        float iw = 0.5f / fmaxf(sqrtf(sw), 1e-12f);
        float4 r;
        r.x = fmaxf(cc.x * ic + w.x * iw, 0.f);
        r.y = fmaxf(cc.y * ic + w.y * iw, 0.f);
        r.z = fmaxf(cc.z * ic + w.z * iw, 0.f);
        r.w = fmaxf(cc.w * ic + w.w * iw, 0.f);
        *(float4*)(pout + (size_t)gw * H + lane * 4) = r;
    } else {
        int node = gw - NP;
        float4 cc = *(const float4*)(Or_ + (size_t)node * H + lane * 4);
        float sc = cc.x*cc.x + cc.y*cc.y + cc.z*cc.z + cc.w*cc.w;
#pragma unroll
        for (int o = 16; o > 0; o >>= 1) sc += __shfl_xor_sync(0xffffffffu, sc, o);
        float ic = 1.0f / fmaxf(sqrtf(sc), 1e-12f);
        float4 r;
        r.x = fmaxf(cc.x * ic, 0.f);
        r.y = fmaxf(cc.y * ic, 0.f);
        r.z = fmaxf(cc.z * ic, 0.f);
        r.w = fmaxf(cc.w * ic, 0.f);
        *(float4*)(aout + (size_t)node * H + lane * 4) = r;
    }
}

// ---------------- host launcher ----------------
extern "C" void kernel_launch(void* const* d_in, const int* in_sizes, int n_in,
                              void* d_out, int out_size) {
    const float* x_paper  = (const float*)d_in[0];
    const float* x_author = (const float*)d_in[1];
    const int* cs = (const int*)d_in[2];
    const int* cd = (const int*)d_in[3];
    const int* ws = (const int*)d_in[4];
    const int* wd = (const int*)d_in[5];
    const int* rs = (const int*)d_in[6];
    const int* rd = (const int*)d_in[7];
    const int EC = in_sizes[2];
    const int EW = in_sizes[4];
    const float* W[18];
    for (int i = 0; i < 18; i++) W[i] = (const float*)d_in[8 + i];

    float *acc_c, *acc_w, *acc_r, *Oc, *Ow, *Or_, *xp, *xa, *WhiB, *WloB;
    int *cnt_c, *cnt_w, *cnt_r, *rp_c, *rp_w, *rp_r, *cur_c, *cur_w, *cur_r;
    int *col_c, *col_w, *col_r, *total;
    cudaGetSymbolAddress((void**)&acc_c, g_acc_c);
    cudaGetSymbolAddress((void**)&acc_w, g_acc_w);
    cudaGetSymbolAddress((void**)&acc_r, g_acc_r);
    cudaGetSymbolAddress((void**)&Oc, g_Oc);
    cudaGetSymbolAddress((void**)&Ow, g_Ow);
    cudaGetSymbolAddress((void**)&Or_, g_Or);
    cudaGetSymbolAddress((void**)&xp, g_xp);
    cudaGetSymbolAddress((void**)&xa, g_xa);
    cudaGetSymbolAddress((void**)&WhiB, g_Whi);
    cudaGetSymbolAddress((void**)&WloB, g_Wlo);
    cudaGetSymbolAddress((void**)&cnt_c, g_cnt_c);
    cudaGetSymbolAddress((void**)&cnt_w, g_cnt_w);
    cudaGetSymbolAddress((void**)&cnt_r, g_cnt_r);
    cudaGetSymbolAddress((void**)&rp_c, g_rp_c);
    cudaGetSymbolAddress((void**)&rp_w, g_rp_w);
    cudaGetSymbolAddress((void**)&rp_r, g_rp_r);
    cudaGetSymbolAddress((void**)&cur_c, g_cur_c);
    cudaGetSymbolAddress((void**)&cur_w, g_cur_w);
    cudaGetSymbolAddress((void**)&cur_r, g_cur_r);
    cudaGetSymbolAddress((void**)&col_c, g_col_c);
    cudaGetSymbolAddress((void**)&col_w, g_col_w);
    cudaGetSymbolAddress((void**)&col_r, g_col_r);
    cudaGetSymbolAddress((void**)&total, g_total);

    cudaFuncSetAttribute(sage_gemm_all, cudaFuncAttributeMaxDynamicSharedMemorySize, SM_GEMM_BYTES);

    // ---- CSR build (merged) ----
    cudaMemsetAsync(cnt_c, 0, NP * sizeof(int));
    cudaMemsetAsync(cnt_w, 0, NP * sizeof(int));
    cudaMemsetAsync(cnt_r, 0, NA * sizeof(int));
    cudaMemsetAsync(total, 0, 3 * sizeof(int));
    const int ETOT = EC + 2 * EW;
    counti_all<<<(ETOT + 255) / 256, 256>>>(cd, wd, rd, cnt_c, cnt_w, cnt_r, EC, EW);
    assign_all<<<(2 * NP + NA + 255) / 256, 256>>>(cnt_c, cnt_w, cnt_r,
                                                   rp_c, rp_w, rp_r,
                                                   cur_c, cur_w, cur_r, total);
    fill_all<<<(ETOT + 255) / 256, 256>>>(cs, cd, ws, wd, rs, rd,
                                          cur_c, cur_w, cur_r, col_c, col_w, col_r, EC, EW);

    // ---- weight split (merged, 6 matrices) ----
    {
        PrepArgs pa;
        for (int l = 0; l < 2; l++)
            for (int t = 0; t < 3; t++) {
                pa.Wl[l * 3 + t] = W[l * 9 + t * 3 + 0];
                pa.Wr[l * 3 + t] = W[l * 9 + t * 3 + 2];
            }
        prep_all<<<(6 * 32768) / 256, 256>>>(pa, WhiB, WloB);
    }

    const float* xpl = x_paper;
    const float* xal = x_author;
    for (int l = 0; l < 2; l++) {
        aggregate_all<<<((2 * NP + NA) * 32 + 255) / 256, 256>>>(
            xpl, xal, rp_c, rp_w, rp_r, cnt_c, cnt_w, cnt_r,
            col_c, col_w, col_r, acc_c, acc_w, acc_r);

        sage_gemm_all<<<GC + GW + GR, 256, SM_GEMM_BYTES>>>(
            acc_c, acc_w, acc_r, xpl, xal,
            WhiB + l * 3 * 32768, WloB + l * 3 * 32768,
            W[l * 9 + 1], W[l * 9 + 4], W[l * 9 + 7],
            Oc, Ow, Or_);

        float* po = (l == 1) ? (float*)d_out : xp;
        float* ao = (l == 1) ? ((float*)d_out + (size_t)NP * H) : xa;
        finalize_all<<<((NP + NA) * 32 + 255) / 256, 256>>>(Oc, Ow, Or_, po, ao);

        xpl = xp;
        xal = xa;
    }
    (void)n_in; (void)out_size; (void)x_author;
}

// round 11
// speedup vs baseline: 1.4264x; 1.1027x over previous
#include <cuda_runtime.h>
#include <cstdint>

#define NP 100000
#define NA 50000
#define H  128
#define EC_MAX 1000000
#define EW_MAX 320000

// ---------------- device scratch ----------------
__device__ float g_acc_c[(size_t)NP * H];
__device__ float g_acc_w[(size_t)NP * H];
__device__ float g_acc_r[(size_t)NA * H];
__device__ float g_Oc[(size_t)NP * H];
__device__ float g_Ow[(size_t)NP * H];
__device__ float g_Or[(size_t)NA * H];
__device__ float g_xp[(size_t)NP * H];
__device__ float g_xa[(size_t)NA * H];
__device__ float g_Whi[6][256 * 128];   // [k][n] tf32-rounded weights
// CSR
__device__ int g_cnt_c[NP], g_cnt_w[NP], g_cnt_r[NA];
__device__ int g_rp_c[NP], g_rp_w[NP], g_rp_r[NA];
__device__ int g_cur_c[NP], g_cur_w[NP], g_cur_r[NA];
__device__ int g_col_c[EC_MAX], g_col_w[EW_MAX], g_col_r[EW_MAX];
__device__ int g_total[3];

// ---------------- helpers ----------------
__device__ __forceinline__ uint32_t f2tf_u(float f) {
    uint32_t r;
    asm("cvt.rna.tf32.f32 %0, %1;" : "=r"(r) : "f"(f));
    return r;
}
__device__ __forceinline__ float f2tf_f(float f) { return __uint_as_float(f2tf_u(f)); }

// ---------------- CSR build ----------------
__global__ void counti_kernel(const int* __restrict__ dst, int* __restrict__ cnt, int nE) {
    int e = blockIdx.x * blockDim.x + threadIdx.x;
    if (e < nE) atomicAdd(&cnt[dst[e]], 1);
}

__global__ void assign_kernel(const int* __restrict__ cnt, int* __restrict__ rp,
                              int* __restrict__ cur, int* __restrict__ total, int n) {
    int i = blockIdx.x * blockDim.x + threadIdx.x;
    int lane = threadIdx.x & 31;
    int v = (i < n) ? cnt[i] : 0;
    int incl = v;
#pragma unroll
    for (int o = 1; o < 32; o <<= 1) {
        int t = __shfl_up_sync(0xffffffffu, incl, o);
        if (lane >= o) incl += t;
    }
    int wsum = __shfl_sync(0xffffffffu, incl, 31);
    int base = 0;
    if (lane == 31) base = atomicAdd(total, wsum);
    base = __shfl_sync(0xffffffffu, base, 31);
    int off = base + incl - v;
    if (i < n) { rp[i] = off; cur[i] = off; }
}

__global__ void fill_kernel(const int* __restrict__ src, const int* __restrict__ dst,
                            int* __restrict__ cur, int* __restrict__ col, int nE) {
    int e = blockIdx.x * blockDim.x + threadIdx.x;
    if (e < nE) {
        int d = dst[e];
        int p = atomicAdd(&cur[d], 1);
        col[p] = src[e];
    }
}

// ---------------- gather-mean aggregation: warp per dst node ----------------
__global__ void aggregate_kernel(const float* __restrict__ x, const int* __restrict__ rp,
                                 const int* __restrict__ cnt, const int* __restrict__ col,
                                 float* __restrict__ acc, int n) {
    int gw   = (blockIdx.x * blockDim.x + threadIdx.x) >> 5;
    int lane = threadIdx.x & 31;
    if (gw >= n) return;
    const int beg = __ldg(&rp[gw]);
    const int deg = __ldg(&cnt[gw]);
    const int end = beg + deg;
    float4 s = make_float4(0.f, 0.f, 0.f, 0.f);
    for (int b = beg; b < end; b += 32) {
        int nb = min(32, end - b);
        int my = (b + lane < end) ? __ldg(&col[b + lane]) : 0;
        for (int j = 0; j < nb; j++) {
            int sn = __shfl_sync(0xffffffffu, my, j);
            float4 v = *(const float4*)(x + (size_t)sn * H + lane * 4);
            s.x += v.x; s.y += v.y; s.z += v.z; s.w += v.w;
        }
    }
    float inv = 1.0f / fmaxf((float)deg, 1.0f);
    s.x *= inv; s.y *= inv; s.z *= inv; s.w *= inv;
    *(float4*)(acc + (size_t)gw * H + lane * 4) = s;
}

// ---------------- weight prep: tf32-round W = [Wl; Wr] into [k][n] ----------------
__global__ void prep_hi(const float* __restrict__ Wl, const float* __restrict__ Wr,
                        float* __restrict__ hi) {
    int i = blockIdx.x * blockDim.x + threadIdx.x;
    if (i < 256 * 128) {
        int k = i >> 7, nn = i & 127;
        float w = (k < 128) ? Wl[k * 128 + nn] : Wr[(k - 128) * 128 + nn];
        hi[i] = f2tf_f(w);
    }
}

// ---------------- single-pass tf32 mma.sync GEMM ----------------
#define AS_STRIDE 36
#define BS_STRIDE 132

__global__ void __launch_bounds__(256, 2) sage_gemm_tc(
    const float* __restrict__ acc, const float* __restrict__ xdst,
    const float* __restrict__ Whi, const float* __restrict__ bias,
    float* __restrict__ O, int n)
{
    __shared__ float bs[128];
    __shared__ float As[128 * AS_STRIDE];
    __shared__ float Bh[32 * BS_STRIDE];

    const int tid  = threadIdx.x;
    const int lane = tid & 31;
    const int wid  = tid >> 5;
    const int wm   = wid & 3;
    const int wn   = wid >> 2;
    const int row0 = blockIdx.x * 128;
    const int rq   = lane >> 2;
    const int cq   = lane & 3;

    if (tid < 128) bs[tid] = __ldg(&bias[tid]);
    __syncthreads();

    float c[2][8][4];
#pragma unroll
    for (int mt = 0; mt < 2; mt++)
#pragma unroll
        for (int nt = 0; nt < 8; nt++) {
            float b0 = bs[wn * 64 + nt * 8 + cq * 2];
            float b1 = bs[wn * 64 + nt * 8 + cq * 2 + 1];
            c[mt][nt][0] = b0; c[mt][nt][1] = b1;
            c[mt][nt][2] = b0; c[mt][nt][3] = b1;
        }

    for (int ch = 0; ch < 8; ch++) {
        const int kc = ch * 32;
        __syncthreads();
        // ---- A tile [128 m][32 k] -> tf32, stride 36 ----
#pragma unroll
        for (int l = 0; l < 4; l++) {
            int idx = tid + l * 256;
            int r   = idx >> 3;
            int klv = (idx & 7) << 2;
            int rg  = row0 + r;
            float4 v = make_float4(0.f, 0.f, 0.f, 0.f);
            if (rg < n) {
                int kg = kc + klv;
                v = (kg < 128)
                    ? *(const float4*)(acc + (size_t)rg * H + kg)
                    : *(const float4*)(xdst + (size_t)rg * H + (kg - 128));
            }
            float* p = As + r * AS_STRIDE + klv;
            p[0] = f2tf_f(v.x); p[1] = f2tf_f(v.y); p[2] = f2tf_f(v.z); p[3] = f2tf_f(v.w);
        }
        // ---- B tile [32 k][128 n], pad 132 (already tf32) ----
#pragma unroll
        for (int l = 0; l < 4; l++) {
            int idx = tid + l * 256;            // 0..1023
            int k   = idx >> 5;
            int nv  = (idx & 31) << 2;
            float4 v = *(const float4*)(Whi + (size_t)(kc + k) * 128 + nv);
            *(float4*)(Bh + k * BS_STRIDE + nv) = v;
        }
        __syncthreads();

        // ---- compute: 4 ksteps of 8 ----
#pragma unroll
        for (int ks = 0; ks < 4; ks++) {
            const int k0 = ks * 8;
            uint32_t au[2][4];
#pragma unroll
            for (int mt = 0; mt < 2; mt++) {
                const float* ap = As + (wm * 32 + mt * 16 + rq) * AS_STRIDE + k0 + cq;
                au[mt][0] = __float_as_uint(ap[0]);
                au[mt][1] = __float_as_uint(ap[8 * AS_STRIDE]);
                au[mt][2] = __float_as_uint(ap[4]);
                au[mt][3] = __float_as_uint(ap[8 * AS_STRIDE + 4]);
            }
#pragma unroll
            for (int nt = 0; nt < 8; nt++) {
                const float* bp = Bh + (k0 + cq) * BS_STRIDE + wn * 64 + nt * 8 + rq;
                uint32_t b0 = __float_as_uint(bp[0]);
                uint32_t b1 = __float_as_uint(bp[4 * BS_STRIDE]);
#pragma unroll
                for (int mt = 0; mt < 2; mt++) {
                    asm volatile(
                        "mma.sync.aligned.m16n8k8.row.col.f32.tf32.tf32.f32 "
                        "{%0, %1, %2, %3}, {%4, %5, %6, %7}, {%8, %9}, {%0, %1, %2, %3};"
                        : "+f"(c[mt][nt][0]), "+f"(c[mt][nt][1]),
                          "+f"(c[mt][nt][2]), "+f"(c[mt][nt][3])
                        : "r"(au[mt][0]), "r"(au[mt][1]), "r"(au[mt][2]), "r"(au[mt][3]),
                          "r"(b0), "r"(b1));
                }
            }
        }
    }

    // ---- plain biased store ----
#pragma unroll
    for (int mt = 0; mt < 2; mt++) {
        int r = row0 + wm * 32 + mt * 16 + rq;
#pragma unroll
        for (int nt = 0; nt < 8; nt++) {
            int col = wn * 64 + nt * 8 + cq * 2;
            if (r < n)
                *(float2*)(O + (size_t)r * H + col) = make_float2(c[mt][nt][0], c[mt][nt][1]);
            if (r + 8 < n)
                *(float2*)(O + (size_t)(r + 8) * H + col) = make_float2(c[mt][nt][2], c[mt][nt][3]);
        }
    }
}

// ---------------- finalize ----------------
__global__ void finalize_paper(const float* __restrict__ Oc, const float* __restrict__ Ow,
                               float* __restrict__ out) {
    int gw   = (blockIdx.x * blockDim.x + threadIdx.x) >> 5;
    int lane = threadIdx.x & 31;
    if (gw >= NP) return;
    float4 cc = *(const float4*)(Oc + (size_t)gw * H + lane * 4);
    float4 w = *(const float4*)(Ow + (size_t)gw * H + lane * 4);
    float sc = cc.x*cc.x + cc.y*cc.y + cc.z*cc.z + cc.w*cc.w;
    float sw = w.x*w.x + w.y*w.y + w.z*w.z + w.w*w.w;
#pragma unroll
    for (int o = 16; o > 0; o >>= 1) {
        sc += __shfl_xor_sync(0xffffffffu, sc, o);
        sw += __shfl_xor_sync(0xffffffffu, sw, o);
    }
    float ic = 0.5f / fmaxf(sqrtf(sc), 1e-12f);
    float iw = 0.5f / fmaxf(sqrtf(sw), 1e-12f);
    float4 r;
    r.x = fmaxf(cc.x * ic + w.x * iw, 0.f);
    r.y = fmaxf(cc.y * ic + w.y * iw, 0.f);
    r.z = fmaxf(cc.z * ic + w.z * iw, 0.f);
    r.w = fmaxf(cc.w * ic + w.w * iw, 0.f);
    *(float4*)(out + (size_t)gw * H + lane * 4) = r;
}
__global__ void finalize_author(const float* __restrict__ Or, float* __restrict__ out) {
    int gw   = (blockIdx.x * blockDim.x + threadIdx.x) >> 5;
    int lane = threadIdx.x & 31;
    if (gw >= NA) return;
    float4 cc = *(const float4*)(Or + (size_t)gw * H + lane * 4);
    float sc = cc.x*cc.x + cc.y*cc.y + cc.z*cc.z + cc.w*cc.w;
#pragma unroll
    for (int o = 16; o > 0; o >>= 1) sc += __shfl_xor_sync(0xffffffffu, sc, o);
    float ic = 1.0f / fmaxf(sqrtf(sc), 1e-12f);
    float4 r;
    r.x = fmaxf(cc.x * ic, 0.f);
    r.y = fmaxf(cc.y * ic, 0.f);
    r.z = fmaxf(cc.z * ic, 0.f);
    r.w = fmaxf(cc.w * ic, 0.f);
    *(float4*)(out + (size_t)gw * H + lane * 4) = r;
}

// ---------------- host launcher ----------------
extern "C" void kernel_launch(void* const* d_in, const int* in_sizes, int n_in,
                              void* d_out, int out_size) {
    const float* x_paper  = (const float*)d_in[0];
    const float* x_author = (const float*)d_in[1];
    const int* cs = (const int*)d_in[2];
    const int* cd = (const int*)d_in[3];
    const int* ws = (const int*)d_in[4];
    const int* wd = (const int*)d_in[5];
    const int* rs = (const int*)d_in[6];
    const int* rd = (const int*)d_in[7];
    const int EC = in_sizes[2];
    const int EW = in_sizes[4];
    const float* W[18];
    for (int i = 0; i < 18; i++) W[i] = (const float*)d_in[8 + i];

    float *acc_c, *acc_w, *acc_r, *Oc, *Ow, *Or, *xp, *xa, *WhiB;
    int *cnt_c, *cnt_w, *cnt_r, *rp_c, *rp_w, *rp_r, *cur_c, *cur_w, *cur_r;
    int *col_c, *col_w, *col_r, *total;
    cudaGetSymbolAddress((void**)&acc_c, g_acc_c);
    cudaGetSymbolAddress((void**)&acc_w, g_acc_w);
    cudaGetSymbolAddress((void**)&acc_r, g_acc_r);
    cudaGetSymbolAddress((void**)&Oc, g_Oc);
    cudaGetSymbolAddress((void**)&Ow, g_Ow);
    cudaGetSymbolAddress((void**)&Or, g_Or);
    cudaGetSymbolAddress((void**)&xp, g_xp);
    cudaGetSymbolAddress((void**)&xa, g_xa);
    cudaGetSymbolAddress((void**)&WhiB, g_Whi);
    cudaGetSymbolAddress((void**)&cnt_c, g_cnt_c);
    cudaGetSymbolAddress((void**)&cnt_w, g_cnt_w);
    cudaGetSymbolAddress((void**)&cnt_r, g_cnt_r);
    cudaGetSymbolAddress((void**)&rp_c, g_rp_c);
    cudaGetSymbolAddress((void**)&rp_w, g_rp_w);
    cudaGetSymbolAddress((void**)&rp_r, g_rp_r);
    cudaGetSymbolAddress((void**)&cur_c, g_cur_c);
    cudaGetSymbolAddress((void**)&cur_w, g_cur_w);
    cudaGetSymbolAddress((void**)&cur_r, g_cur_r);
    cudaGetSymbolAddress((void**)&col_c, g_col_c);
    cudaGetSymbolAddress((void**)&col_w, g_col_w);
    cudaGetSymbolAddress((void**)&col_r, g_col_r);
    cudaGetSymbolAddress((void**)&total, g_total);

    // ---- CSR build ----
    cudaMemsetAsync(cnt_c, 0, NP * sizeof(int));
    cudaMemsetAsync(cnt_w, 0, NP * sizeof(int));
    cudaMemsetAsync(cnt_r, 0, NA * sizeof(int));
    cudaMemsetAsync(total, 0, 3 * sizeof(int));
    counti_kernel<<<(EC + 255) / 256, 256>>>(cd, cnt_c, EC);
    counti_kernel<<<(EW + 255) / 256, 256>>>(wd, cnt_w, EW);
    counti_kernel<<<(EW + 255) / 256, 256>>>(rd, cnt_r, EW);
    assign_kernel<<<(NP + 255) / 256, 256>>>(cnt_c, rp_c, cur_c, total + 0, NP);
    assign_kernel<<<(NP + 255) / 256, 256>>>(cnt_w, rp_w, cur_w, total + 1, NP);
    assign_kernel<<<(NA + 255) / 256, 256>>>(cnt_r, rp_r, cur_r, total + 2, NA);
    fill_kernel<<<(EC + 255) / 256, 256>>>(cs, cd, cur_c, col_c, EC);
    fill_kernel<<<(EW + 255) / 256, 256>>>(ws, wd, cur_w, col_w, EW);
    fill_kernel<<<(EW + 255) / 256, 256>>>(rs, rd, cur_r, col_r, EW);

    // ---- weight prep (tf32 round once) ----
    for (int l = 0; l < 2; l++)
        for (int t = 0; t < 3; t++) {
            const float* Wl = W[l * 9 + t * 3 + 0];
            const float* Wr = W[l * 9 + t * 3 + 2];
            prep_hi<<<128, 256>>>(Wl, Wr, WhiB + (l * 3 + t) * 256 * 128);
        }

    const float* xpl = x_paper;
    const float* xal = x_author;
    for (int l = 0; l < 2; l++) {
        aggregate_kernel<<<(NP * 32 + 255) / 256, 256>>>(xpl, rp_c, cnt_c, col_c, acc_c, NP);
        aggregate_kernel<<<(NP * 32 + 255) / 256, 256>>>(xal, rp_w, cnt_w, col_w, acc_w, NP);
        aggregate_kernel<<<(NA * 32 + 255) / 256, 256>>>(xpl, rp_r, cnt_r, col_r, acc_r, NA);

        const float* Whc = WhiB + (l * 3 + 0) * 256 * 128;
        const float* Whw = WhiB + (l * 3 + 1) * 256 * 128;
        const float* Whr = WhiB + (l * 3 + 2) * 256 * 128;

        sage_gemm_tc<<<(NP + 127) / 128, 256>>>(acc_c, xpl, Whc, W[l * 9 + 1], Oc, NP);
        sage_gemm_tc<<<(NP + 127) / 128, 256>>>(acc_w, xpl, Whw, W[l * 9 + 4], Ow, NP);
        sage_gemm_tc<<<(NA + 127) / 128, 256>>>(acc_r, xal, Whr, W[l * 9 + 7], Or, NA);

        float* po = (l == 1) ? (float*)d_out : xp;
        float* ao = (l == 1) ? ((float*)d_out + (size_t)NP * H) : xa;
        finalize_paper<<<(NP * 32 + 255) / 256, 256>>>(Oc, Ow, po);
        finalize_author<<<(NA * 32 + 255) / 256, 256>>>(Or, ao);

        xpl = xp;
        xal = xa;
    }
    (void)n_in; (void)out_size; (void)x_author;
}

// round 12
// speedup vs baseline: 1.7362x; 1.2172x over previous
#include <cuda_runtime.h>
#include <cstdint>

#define NP 100000
#define NA 50000
#define H  128
#define EC_MAX 1000000
#define EW_MAX 320000

// ---------------- device scratch ----------------
__device__ float g_acc_c[(size_t)NP * H];
__device__ float g_acc_w[(size_t)NP * H];
__device__ float g_acc_r[(size_t)NA * H];
__device__ float g_Oc[(size_t)NP * H];
__device__ float g_Ow[(size_t)NP * H];
__device__ float g_Or[(size_t)NA * H];
__device__ float g_xp[(size_t)NP * H];
__device__ float g_xa[(size_t)NA * H];
__device__ float g_Whi[6][256 * 128];   // [k][n] tf32-rounded weights
// CSR
__device__ int g_cnt_c[NP], g_cnt_w[NP], g_cnt_r[NA];
__device__ int g_rp_c[NP], g_rp_w[NP], g_rp_r[NA];
__device__ int g_cur_c[NP], g_cur_w[NP], g_cur_r[NA];
__device__ int g_col_c[EC_MAX], g_col_w[EW_MAX], g_col_r[EW_MAX];
__device__ int g_total[3];

// ---------------- helpers ----------------
__device__ __forceinline__ uint32_t f2tf_u(float f) {
    uint32_t r;
    asm("cvt.rna.tf32.f32 %0, %1;" : "=r"(r) : "f"(f));
    return r;
}
__device__ __forceinline__ float f2tf_f(float f) { return __uint_as_float(f2tf_u(f)); }

// ---------------- CSR build ----------------
__global__ void counti_kernel(const int* __restrict__ dst, int* __restrict__ cnt, int nE) {
    int e = blockIdx.x * blockDim.x + threadIdx.x;
    if (e < nE) atomicAdd(&cnt[dst[e]], 1);
}

__global__ void assign_kernel(const int* __restrict__ cnt, int* __restrict__ rp,
                              int* __restrict__ cur, int* __restrict__ total, int n) {
    int i = blockIdx.x * blockDim.x + threadIdx.x;
    int lane = threadIdx.x & 31;
    int v = (i < n) ? cnt[i] : 0;
    int incl = v;
#pragma unroll
    for (int o = 1; o < 32; o <<= 1) {
        int t = __shfl_up_sync(0xffffffffu, incl, o);
        if (lane >= o) incl += t;
    }
    int wsum = __shfl_sync(0xffffffffu, incl, 31);
    int base = 0;
    if (lane == 31) base = atomicAdd(total, wsum);
    base = __shfl_sync(0xffffffffu, base, 31);
    int off = base + incl - v;
    if (i < n) { rp[i] = off; cur[i] = off; }
}

__global__ void fill_kernel(const int* __restrict__ src, const int* __restrict__ dst,
                            int* __restrict__ cur, int* __restrict__ col, int nE) {
    int e = blockIdx.x * blockDim.x + threadIdx.x;
    if (e < nE) {
        int d = dst[e];
        int p = atomicAdd(&cur[d], 1);
        col[p] = src[e];
    }
}

// ---------------- gather-mean aggregation: warp per dst node ----------------
__global__ void aggregate_kernel(const float* __restrict__ x, const int* __restrict__ rp,
                                 const int* __restrict__ cnt, const int* __restrict__ col,
                                 float* __restrict__ acc, int n) {
    int gw   = (blockIdx.x * blockDim.x + threadIdx.x) >> 5;
    int lane = threadIdx.x & 31;
    if (gw >= n) return;
    const int beg = __ldg(&rp[gw]);
    const int deg = __ldg(&cnt[gw]);
    const int end = beg + deg;
    float4 s = make_float4(0.f, 0.f, 0.f, 0.f);
    for (int b = beg; b < end; b += 32) {
        int nb = min(32, end - b);
        int my = (b + lane < end) ? __ldg(&col[b + lane]) : 0;
        for (int j = 0; j < nb; j++) {
            int sn = __shfl_sync(0xffffffffu, my, j);
            float4 v = *(const float4*)(x + (size_t)sn * H + lane * 4);
            s.x += v.x; s.y += v.y; s.z += v.z; s.w += v.w;
        }
    }
    float inv = 1.0f / fmaxf((float)deg, 1.0f);
    s.x *= inv; s.y *= inv; s.z *= inv; s.w *= inv;
    *(float4*)(acc + (size_t)gw * H + lane * 4) = s;
}

// ---------------- weight prep: tf32-round W = [Wl; Wr] into [k][n] ----------------
__global__ void prep_hi(const float* __restrict__ Wl, const float* __restrict__ Wr,
                        float* __restrict__ hi) {
    int i = blockIdx.x * blockDim.x + threadIdx.x;
    if (i < 256 * 128) {
        int k = i >> 7, nn = i & 127;
        float w = (k < 128) ? Wl[k * 128 + nn] : Wr[(k - 128) * 128 + nn];
        hi[i] = f2tf_f(w);
    }
}

// ---------------- single-pass tf32 mma.sync GEMM + A reg double-buffer ----------------
#define AS_STRIDE 36
#define BS_STRIDE 132

__global__ void __launch_bounds__(256, 2) sage_gemm_tc(
    const float* __restrict__ acc, const float* __restrict__ xdst,
    const float* __restrict__ Whi, const float* __restrict__ bias,
    float* __restrict__ O, int n)
{
    __shared__ float bs[128];
    __shared__ float As[128 * AS_STRIDE];
    __shared__ float Bh[32 * BS_STRIDE];

    const int tid  = threadIdx.x;
    const int lane = tid & 31;
    const int wid  = tid >> 5;
    const int wm   = wid & 3;
    const int wn   = wid >> 2;
    const int row0 = blockIdx.x * 128;
    const int rq   = lane >> 2;
    const int cq   = lane & 3;

    if (tid < 128) bs[tid] = __ldg(&bias[tid]);
    __syncthreads();

    float c[2][8][4];
#pragma unroll
    for (int mt = 0; mt < 2; mt++)
#pragma unroll
        for (int nt = 0; nt < 8; nt++) {
            float b0 = bs[wn * 64 + nt * 8 + cq * 2];
            float b1 = bs[wn * 64 + nt * 8 + cq * 2 + 1];
            c[mt][nt][0] = b0; c[mt][nt][1] = b1;
            c[mt][nt][2] = b0; c[mt][nt][3] = b1;
        }

    // prefetch chunk 0's A tile into registers
    float4 areg[4];
#pragma unroll
    for (int l = 0; l < 4; l++) {
        int idx = tid + l * 256;
        int r   = idx >> 3;
        int klv = (idx & 7) << 2;
        int rg  = row0 + r;
        areg[l] = make_float4(0.f, 0.f, 0.f, 0.f);
        if (rg < n)
            areg[l] = *(const float4*)(acc + (size_t)rg * H + klv);   // kc=0 -> always acc side
    }

    for (int ch = 0; ch < 8; ch++) {
        __syncthreads();   // previous chunk's As/Bh reads done
        // ---- store prefetched A (convert to tf32), stride 36 ----
#pragma unroll
        for (int l = 0; l < 4; l++) {
            int idx = tid + l * 256;
            int r   = idx >> 3;
            int klv = (idx & 7) << 2;
            float* p = As + r * AS_STRIDE + klv;
            p[0] = f2tf_f(areg[l].x); p[1] = f2tf_f(areg[l].y);
            p[2] = f2tf_f(areg[l].z); p[3] = f2tf_f(areg[l].w);
        }
        // ---- B tile [32 k][128 n], pad 132 (already tf32) ----
        {
            const int kc = ch * 32;
#pragma unroll
            for (int l = 0; l < 4; l++) {
                int idx = tid + l * 256;            // 0..1023
                int k   = idx >> 5;
                int nv  = (idx & 31) << 2;
                float4 v = *(const float4*)(Whi + (size_t)(kc + k) * 128 + nv);
                *(float4*)(Bh + k * BS_STRIDE + nv) = v;
            }
        }
        // ---- prefetch next chunk's A into registers ----
        if (ch < 7) {
            const int kc = (ch + 1) * 32;
#pragma unroll
            for (int l = 0; l < 4; l++) {
                int idx = tid + l * 256;
                int r   = idx >> 3;
                int klv = (idx & 7) << 2;
                int rg  = row0 + r;
                int kg  = kc + klv;
                areg[l] = make_float4(0.f, 0.f, 0.f, 0.f);
                if (rg < n) {
                    areg[l] = (kg < 128)
                        ? *(const float4*)(acc + (size_t)rg * H + kg)
                        : *(const float4*)(xdst + (size_t)rg * H + (kg - 128));
                }
            }
        }
        __syncthreads();

        // ---- compute: 4 ksteps of 8 (inner loop untouched) ----
#pragma unroll
        for (int ks = 0; ks < 4; ks++) {
            const int k0 = ks * 8;
            uint32_t au[2][4];
#pragma unroll
            for (int mt = 0; mt < 2; mt++) {
                const float* ap = As + (wm * 32 + mt * 16 + rq) * AS_STRIDE + k0 + cq;
                au[mt][0] = __float_as_uint(ap[0]);
                au[mt][1] = __float_as_uint(ap[8 * AS_STRIDE]);
                au[mt][2] = __float_as_uint(ap[4]);
                au[mt][3] = __float_as_uint(ap[8 * AS_STRIDE + 4]);
            }
#pragma unroll
            for (int nt = 0; nt < 8; nt++) {
                const float* bp = Bh + (k0 + cq) * BS_STRIDE + wn * 64 + nt * 8 + rq;
                uint32_t b0 = __float_as_uint(bp[0]);
                uint32_t b1 = __float_as_uint(bp[4 * BS_STRIDE]);
#pragma unroll
                for (int mt = 0; mt < 2; mt++) {
                    asm volatile(
                        "mma.sync.aligned.m16n8k8.row.col.f32.tf32.tf32.f32 "
                        "{%0, %1, %2, %3}, {%4, %5, %6, %7}, {%8, %9}, {%0, %1, %2, %3};"
                        : "+f"(c[mt][nt][0]), "+f"(c[mt][nt][1]),
                          "+f"(c[mt][nt][2]), "+f"(c[mt][nt][3])
                        : "r"(au[mt][0]), "r"(au[mt][1]), "r"(au[mt][2]), "r"(au[mt][3]),
                          "r"(b0), "r"(b1));
                }
            }
        }
    }

    // ---- plain biased store ----
#pragma unroll
    for (int mt = 0; mt < 2; mt++) {
        int r = row0 + wm * 32 + mt * 16 + rq;
#pragma unroll
        for (int nt = 0; nt < 8; nt++) {
            int col = wn * 64 + nt * 8 + cq * 2;
            if (r < n)
                *(float2*)(O + (size_t)r * H + col) = make_float2(c[mt][nt][0], c[mt][nt][1]);
            if (r + 8 < n)
                *(float2*)(O + (size_t)(r + 8) * H + col) = make_float2(c[mt][nt][2], c[mt][nt][3]);
        }
    }
}

// ---------------- finalize ----------------
__global__ void finalize_paper(const float* __restrict__ Oc, const float* __restrict__ Ow,
                               float* __restrict__ out) {
    int gw   = (blockIdx.x * blockDim.x + threadIdx.x) >> 5;
    int lane = threadIdx.x & 31;
    if (gw >= NP) return;
    float4 cc = *(const float4*)(Oc + (size_t)gw * H + lane * 4);
    float4 w = *(const float4*)(Ow + (size_t)gw * H + lane * 4);
    float sc = cc.x*cc.x + cc.y*cc.y + cc.z*cc.z + cc.w*cc.w;
    float sw = w.x*w.x + w.y*w.y + w.z*w.z + w.w*w.w;
#pragma unroll
    for (int o = 16; o > 0; o >>= 1) {
        sc += __shfl_xor_sync(0xffffffffu, sc, o);
        sw += __shfl_xor_sync(0xffffffffu, sw, o);
    }
    float ic = 0.5f / fmaxf(sqrtf(sc), 1e-12f);
    float iw = 0.5f / fmaxf(sqrtf(sw), 1e-12f);
    float4 r;
    r.x = fmaxf(cc.x * ic + w.x * iw, 0.f);
    r.y = fmaxf(cc.y * ic + w.y * iw, 0.f);
    r.z = fmaxf(cc.z * ic + w.z * iw, 0.f);
    r.w = fmaxf(cc.w * ic + w.w * iw, 0.f);
    *(float4*)(out + (size_t)gw * H + lane * 4) = r;
}
__global__ void finalize_author(const float* __restrict__ Or, float* __restrict__ out) {
    int gw   = (blockIdx.x * blockDim.x + threadIdx.x) >> 5;
    int lane = threadIdx.x & 31;
    if (gw >= NA) return;
    float4 cc = *(const float4*)(Or + (size_t)gw * H + lane * 4);
    float sc = cc.x*cc.x + cc.y*cc.y + cc.z*cc.z + cc.w*cc.w;
#pragma unroll
    for (int o = 16; o > 0; o >>= 1) sc += __shfl_xor_sync(0xffffffffu, sc, o);
    float ic = 1.0f / fmaxf(sqrtf(sc), 1e-12f);
    float4 r;
    r.x = fmaxf(cc.x * ic, 0.f);
    r.y = fmaxf(cc.y * ic, 0.f);
    r.z = fmaxf(cc.z * ic, 0.f);
    r.w = fmaxf(cc.w * ic, 0.f);
    *(float4*)(out + (size_t)gw * H + lane * 4) = r;
}

// ---------------- host launcher ----------------
extern "C" void kernel_launch(void* const* d_in, const int* in_sizes, int n_in,
                              void* d_out, int out_size) {
    const float* x_paper  = (const float*)d_in[0];
    const float* x_author = (const float*)d_in[1];
    const int* cs = (const int*)d_in[2];
    const int* cd = (const int*)d_in[3];
    const int* ws = (const int*)d_in[4];
    const int* wd = (const int*)d_in[5];
    const int* rs = (const int*)d_in[6];
    const int* rd = (const int*)d_in[7];
    const int EC = in_sizes[2];
    const int EW = in_sizes[4];
    const float* W[18];
    for (int i = 0; i < 18; i++) W[i] = (const float*)d_in[8 + i];

    float *acc_c, *acc_w, *acc_r, *Oc, *Ow, *Or, *xp, *xa, *WhiB;
    int *cnt_c, *cnt_w, *cnt_r, *rp_c, *rp_w, *rp_r, *cur_c, *cur_w, *cur_r;
    int *col_c, *col_w, *col_r, *total;
    cudaGetSymbolAddress((void**)&acc_c, g_acc_c);
    cudaGetSymbolAddress((void**)&acc_w, g_acc_w);
    cudaGetSymbolAddress((void**)&acc_r, g_acc_r);
    cudaGetSymbolAddress((void**)&Oc, g_Oc);
    cudaGetSymbolAddress((void**)&Ow, g_Ow);
    cudaGetSymbolAddress((void**)&Or, g_Or);
    cudaGetSymbolAddress((void**)&xp, g_xp);
    cudaGetSymbolAddress((void**)&xa, g_xa);
    cudaGetSymbolAddress((void**)&WhiB, g_Whi);
    cudaGetSymbolAddress((void**)&cnt_c, g_cnt_c);
    cudaGetSymbolAddress((void**)&cnt_w, g_cnt_w);
    cudaGetSymbolAddress((void**)&cnt_r, g_cnt_r);
    cudaGetSymbolAddress((void**)&rp_c, g_rp_c);
    cudaGetSymbolAddress((void**)&rp_w, g_rp_w);
    cudaGetSymbolAddress((void**)&rp_r, g_rp_r);
    cudaGetSymbolAddress((void**)&cur_c, g_cur_c);
    cudaGetSymbolAddress((void**)&cur_w, g_cur_w);
    cudaGetSymbolAddress((void**)&cur_r, g_cur_r);
    cudaGetSymbolAddress((void**)&col_c, g_col_c);
    cudaGetSymbolAddress((void**)&col_w, g_col_w);
    cudaGetSymbolAddress((void**)&col_r, g_col_r);
    cudaGetSymbolAddress((void**)&total, g_total);

    // ---- CSR build ----
    cudaMemsetAsync(cnt_c, 0, NP * sizeof(int));
    cudaMemsetAsync(cnt_w, 0, NP * sizeof(int));
    cudaMemsetAsync(cnt_r, 0, NA * sizeof(int));
    cudaMemsetAsync(total, 0, 3 * sizeof(int));
    counti_kernel<<<(EC + 255) / 256, 256>>>(cd, cnt_c, EC);
    counti_kernel<<<(EW + 255) / 256, 256>>>(wd, cnt_w, EW);
    counti_kernel<<<(EW + 255) / 256, 256>>>(rd, cnt_r, EW);
    assign_kernel<<<(NP + 255) / 256, 256>>>(cnt_c, rp_c, cur_c, total + 0, NP);
    assign_kernel<<<(NP + 255) / 256, 256>>>(cnt_w, rp_w, cur_w, total + 1, NP);
    assign_kernel<<<(NA + 255) / 256, 256>>>(cnt_r, rp_r, cur_r, total + 2, NA);
    fill_kernel<<<(EC + 255) / 256, 256>>>(cs, cd, cur_c, col_c, EC);
    fill_kernel<<<(EW + 255) / 256, 256>>>(ws, wd, cur_w, col_w, EW);
    fill_kernel<<<(EW + 255) / 256, 256>>>(rs, rd, cur_r, col_r, EW);

    // ---- weight prep (tf32 round once) ----
    for (int l = 0; l < 2; l++)
        for (int t = 0; t < 3; t++) {
            const float* Wl = W[l * 9 + t * 3 + 0];
            const float* Wr = W[l * 9 + t * 3 + 2];
            prep_hi<<<128, 256>>>(Wl, Wr, WhiB + (l * 3 + t) * 256 * 128);
        }

    const float* xpl = x_paper;
    const float* xal = x_author;
    for (int l = 0; l < 2; l++) {
        aggregate_kernel<<<(NP * 32 + 255) / 256, 256>>>(xpl, rp_c, cnt_c, col_c, acc_c, NP);
        aggregate_kernel<<<(NP * 32 + 255) / 256, 256>>>(xal, rp_w, cnt_w, col_w, acc_w, NP);
        aggregate_kernel<<<(NA * 32 + 255) / 256, 256>>>(xpl, rp_r, cnt_r, col_r, acc_r, NA);

        const float* Whc = WhiB + (l * 3 + 0) * 256 * 128;
        const float* Whw = WhiB + (l * 3 + 1) * 256 * 128;
        const float* Whr = WhiB + (l * 3 + 2) * 256 * 128;

        sage_gemm_tc<<<(NP + 127) / 128, 256>>>(acc_c, xpl, Whc, W[l * 9 + 1], Oc, NP);
        sage_gemm_tc<<<(NP + 127) / 128, 256>>>(acc_w, xpl, Whw, W[l * 9 + 4], Ow, NP);
        sage_gemm_tc<<<(NA + 127) / 128, 256>>>(acc_r, xal, Whr, W[l * 9 + 7], Or, NA);

        float* po = (l == 1) ? (float*)d_out : xp;
        float* ao = (l == 1) ? ((float*)d_out + (size_t)NP * H) : xa;
        finalize_paper<<<(NP * 32 + 255) / 256, 256>>>(Oc, Ow, po);
        finalize_author<<<(NA * 32 + 255) / 256, 256>>>(Or, ao);

        xpl = xp;
        xal = xa;
    }
    (void)n_in; (void)out_size; (void)x_author;
}

// round 13
// speedup vs baseline: 1.8575x; 1.0699x over previous
#include <cuda_runtime.h>
#include <cstdint>

#define NP 100000
#define NA 50000
#define H  128
#define EC_MAX 1000000
#define EW_MAX 320000

// ---------------- device scratch ----------------
__device__ float g_acc_c[(size_t)NP * H];
__device__ float g_acc_w[(size_t)NP * H];
__device__ float g_acc_r[(size_t)NA * H];
__device__ float g_Oc[(size_t)NP * H];      // cites: 0.5 * O / ||O||
__device__ float g_xp[(size_t)NP * H];
__device__ float g_xa[(size_t)NA * H];
__device__ float g_Whi[6][256 * 128];       // [k][n] tf32-rounded weights
// CSR
__device__ int g_cnt_c[NP], g_cnt_w[NP], g_cnt_r[NA];
__device__ int g_rp_c[NP], g_rp_w[NP], g_rp_r[NA];
__device__ int g_cur_c[NP], g_cur_w[NP], g_cur_r[NA];
__device__ int g_col_c[EC_MAX], g_col_w[EW_MAX], g_col_r[EW_MAX];
__device__ int g_total[3];

// ---------------- helpers ----------------
__device__ __forceinline__ uint32_t f2tf_u(float f) {
    uint32_t r;
    asm("cvt.rna.tf32.f32 %0, %1;" : "=r"(r) : "f"(f));
    return r;
}
__device__ __forceinline__ float f2tf_f(float f) { return __uint_as_float(f2tf_u(f)); }

// ---------------- CSR build ----------------
__global__ void counti_kernel(const int* __restrict__ dst, int* __restrict__ cnt, int nE) {
    int e = blockIdx.x * blockDim.x + threadIdx.x;
    if (e < nE) atomicAdd(&cnt[dst[e]], 1);
}

__global__ void assign_kernel(const int* __restrict__ cnt, int* __restrict__ rp,
                              int* __restrict__ cur, int* __restrict__ total, int n) {
    int i = blockIdx.x * blockDim.x + threadIdx.x;
    int lane = threadIdx.x & 31;
    int v = (i < n) ? cnt[i] : 0;
    int incl = v;
#pragma unroll
    for (int o = 1; o < 32; o <<= 1) {
        int t = __shfl_up_sync(0xffffffffu, incl, o);
        if (lane >= o) incl += t;
    }
    int wsum = __shfl_sync(0xffffffffu, incl, 31);
    int base = 0;
    if (lane == 31) base = atomicAdd(total, wsum);
    base = __shfl_sync(0xffffffffu, base, 31);
    int off = base + incl - v;
    if (i < n) { rp[i] = off; cur[i] = off; }
}

__global__ void fill_kernel(const int* __restrict__ src, const int* __restrict__ dst,
                            int* __restrict__ cur, int* __restrict__ col, int nE) {
    int e = blockIdx.x * blockDim.x + threadIdx.x;
    if (e < nE) {
        int d = dst[e];
        int p = atomicAdd(&cur[d], 1);
        col[p] = src[e];
    }
}

// ---------------- gather-mean aggregation: warp per dst node ----------------
__global__ void aggregate_kernel(const float* __restrict__ x, const int* __restrict__ rp,
                                 const int* __restrict__ cnt, const int* __restrict__ col,
                                 float* __restrict__ acc, int n) {
    int gw   = (blockIdx.x * blockDim.x + threadIdx.x) >> 5;
    int lane = threadIdx.x & 31;
    if (gw >= n) return;
    const int beg = __ldg(&rp[gw]);
    const int deg = __ldg(&cnt[gw]);
    const int end = beg + deg;
    float4 s = make_float4(0.f, 0.f, 0.f, 0.f);
    for (int b = beg; b < end; b += 32) {
        int nb = min(32, end - b);
        int my = (b + lane < end) ? __ldg(&col[b + lane]) : 0;
        for (int j = 0; j < nb; j++) {
            int sn = __shfl_sync(0xffffffffu, my, j);
            float4 v = *(const float4*)(x + (size_t)sn * H + lane * 4);
            s.x += v.x; s.y += v.y; s.z += v.z; s.w += v.w;
        }
    }
    float inv = 1.0f / fmaxf((float)deg, 1.0f);
    s.x *= inv; s.y *= inv; s.z *= inv; s.w *= inv;
    *(float4*)(acc + (size_t)gw * H + lane * 4) = s;
}

// ---------------- weight prep: tf32-round W = [Wl; Wr] into [k][n] ----------------
__global__ void prep_hi(const float* __restrict__ Wl, const float* __restrict__ Wr,
                        float* __restrict__ hi) {
    int i = blockIdx.x * blockDim.x + threadIdx.x;
    if (i < 256 * 128) {
        int k = i >> 7, nn = i & 127;
        float w = (k < 128) ? Wl[k * 128 + nn] : Wr[(k - 128) * 128 + nn];
        hi[i] = f2tf_f(w);
    }
}

// ---------------- single-pass tf32 GEMM + A reg prefetch + fused normalize ----------------
// MODE 0: out = O*0.5/||O||              (cites -> Oc buffer)
// MODE 1: out = relu(prev + O*0.5/||O||) (writes -> paper out)
// MODE 2: out = relu(O/||O||)            (rev -> author out)
#define AS_STRIDE 36
#define BS_STRIDE 132

template <int MODE>
__global__ void __launch_bounds__(256, 2) sage_gemm_tc(
    const float* __restrict__ acc, const float* __restrict__ xdst,
    const float* __restrict__ Whi, const float* __restrict__ bias,
    const float* __restrict__ prev, float* __restrict__ O, int n)
{
    __shared__ float bs[128];
    __shared__ float As[128 * AS_STRIDE];
    __shared__ float Bh[32 * BS_STRIDE];
    __shared__ float rowsq[256];

    const int tid  = threadIdx.x;
    const int lane = tid & 31;
    const int wid  = tid >> 5;
    const int wm   = wid & 3;
    const int wn   = wid >> 2;
    const int row0 = blockIdx.x * 128;
    const int rq   = lane >> 2;
    const int cq   = lane & 3;

    if (tid < 128) bs[tid] = __ldg(&bias[tid]);
    __syncthreads();

    float c[2][8][4];
#pragma unroll
    for (int mt = 0; mt < 2; mt++)
#pragma unroll
        for (int nt = 0; nt < 8; nt++) {
            float b0 = bs[wn * 64 + nt * 8 + cq * 2];
            float b1 = bs[wn * 64 + nt * 8 + cq * 2 + 1];
            c[mt][nt][0] = b0; c[mt][nt][1] = b1;
            c[mt][nt][2] = b0; c[mt][nt][3] = b1;
        }

    // prefetch chunk 0's A tile into registers
    float4 areg[4];
#pragma unroll
    for (int l = 0; l < 4; l++) {
        int idx = tid + l * 256;
        int r   = idx >> 3;
        int klv = (idx & 7) << 2;
        int rg  = row0 + r;
        areg[l] = make_float4(0.f, 0.f, 0.f, 0.f);
        if (rg < n)
            areg[l] = *(const float4*)(acc + (size_t)rg * H + klv);
    }

    for (int ch = 0; ch < 8; ch++) {
        __syncthreads();
        // store prefetched A (convert to tf32)
#pragma unroll
        for (int l = 0; l < 4; l++) {
            int idx = tid + l * 256;
            int r   = idx >> 3;
            int klv = (idx & 7) << 2;
            float* p = As + r * AS_STRIDE + klv;
            p[0] = f2tf_f(areg[l].x); p[1] = f2tf_f(areg[l].y);
            p[2] = f2tf_f(areg[l].z); p[3] = f2tf_f(areg[l].w);
        }
        // B tile [32 k][128 n], pad 132 (already tf32)
        {
            const int kc = ch * 32;
#pragma unroll
            for (int l = 0; l < 4; l++) {
                int idx = tid + l * 256;
                int k   = idx >> 5;
                int nv  = (idx & 31) << 2;
                float4 v = *(const float4*)(Whi + (size_t)(kc + k) * 128 + nv);
                *(float4*)(Bh + k * BS_STRIDE + nv) = v;
            }
        }
        // prefetch next chunk's A
        if (ch < 7) {
            const int kc = (ch + 1) * 32;
#pragma unroll
            for (int l = 0; l < 4; l++) {
                int idx = tid + l * 256;
                int r   = idx >> 3;
                int klv = (idx & 7) << 2;
                int rg  = row0 + r;
                int kg  = kc + klv;
                areg[l] = make_float4(0.f, 0.f, 0.f, 0.f);
                if (rg < n) {
                    areg[l] = (kg < 128)
                        ? *(const float4*)(acc + (size_t)rg * H + kg)
                        : *(const float4*)(xdst + (size_t)rg * H + (kg - 128));
                }
            }
        }
        __syncthreads();

        // compute: 4 ksteps of 8
#pragma unroll
        for (int ks = 0; ks < 4; ks++) {
            const int k0 = ks * 8;
            uint32_t au[2][4];
#pragma unroll
            for (int mt = 0; mt < 2; mt++) {
                const float* ap = As + (wm * 32 + mt * 16 + rq) * AS_STRIDE + k0 + cq;
                au[mt][0] = __float_as_uint(ap[0]);
                au[mt][1] = __float_as_uint(ap[8 * AS_STRIDE]);
                au[mt][2] = __float_as_uint(ap[4]);
                au[mt][3] = __float_as_uint(ap[8 * AS_STRIDE + 4]);
            }
#pragma unroll
            for (int nt = 0; nt < 8; nt++) {
                const float* bp = Bh + (k0 + cq) * BS_STRIDE + wn * 64 + nt * 8 + rq;
                uint32_t b0 = __float_as_uint(bp[0]);
                uint32_t b1 = __float_as_uint(bp[4 * BS_STRIDE]);
#pragma unroll
                for (int mt = 0; mt < 2; mt++) {
                    asm volatile(
                        "mma.sync.aligned.m16n8k8.row.col.f32.tf32.tf32.f32 "
                        "{%0, %1, %2, %3}, {%4, %5, %6, %7}, {%8, %9}, {%0, %1, %2, %3};"
                        : "+f"(c[mt][nt][0]), "+f"(c[mt][nt][1]),
                          "+f"(c[mt][nt][2]), "+f"(c[mt][nt][3])
                        : "r"(au[mt][0]), "r"(au[mt][1]), "r"(au[mt][2]), "r"(au[mt][3]),
                          "r"(b0), "r"(b1));
                }
            }
        }
    }

    // ---- fused epilogue: per-row L2 norm across both wn halves, scale/combine ----
    __syncthreads();
#pragma unroll
    for (int mt = 0; mt < 2; mt++)
#pragma unroll
        for (int hm = 0; hm < 2; hm++) {
            float s = 0.f;
#pragma unroll
            for (int nt = 0; nt < 8; nt++) {
                float a = c[mt][nt][hm * 2], b = c[mt][nt][hm * 2 + 1];
                s += a * a + b * b;
            }
            s += __shfl_xor_sync(0xffffffffu, s, 1);
            s += __shfl_xor_sync(0xffffffffu, s, 2);
            if (cq == 0) rowsq[wn * 128 + wm * 32 + mt * 16 + hm * 8 + rq] = s;
        }
    __syncthreads();

    const float SC = (MODE == 2) ? 1.0f : 0.5f;
#pragma unroll
    for (int mt = 0; mt < 2; mt++)
#pragma unroll
        for (int hm = 0; hm < 2; hm++) {
            int rl = wm * 32 + mt * 16 + hm * 8 + rq;
            int rg = row0 + rl;
            float tot = rowsq[rl] + rowsq[128 + rl];
            float f = SC / fmaxf(sqrtf(tot), 1e-12f);
            if (rg < n) {
#pragma unroll
                for (int nt = 0; nt < 8; nt++) {
                    int col = wn * 64 + nt * 8 + cq * 2;
                    float v0 = c[mt][nt][hm * 2] * f;
                    float v1 = c[mt][nt][hm * 2 + 1] * f;
                    if (MODE == 1) {
                        float2 p = *(const float2*)(prev + (size_t)rg * H + col);
                        v0 = fmaxf(p.x + v0, 0.f);
                        v1 = fmaxf(p.y + v1, 0.f);
                    } else if (MODE == 2) {
                        v0 = fmaxf(v0, 0.f);
                        v1 = fmaxf(v1, 0.f);
                    }
                    *(float2*)(O + (size_t)rg * H + col) = make_float2(v0, v1);
                }
            }
        }
}

// ---------------- host launcher ----------------
extern "C" void kernel_launch(void* const* d_in, const int* in_sizes, int n_in,
                              void* d_out, int out_size) {
    const float* x_paper  = (const float*)d_in[0];
    const float* x_author = (const float*)d_in[1];
    const int* cs = (const int*)d_in[2];
    const int* cd = (const int*)d_in[3];
    const int* ws = (const int*)d_in[4];
    const int* wd = (const int*)d_in[5];
    const int* rs = (const int*)d_in[6];
    const int* rd = (const int*)d_in[7];
    const int EC = in_sizes[2];
    const int EW = in_sizes[4];
    const float* W[18];
    for (int i = 0; i < 18; i++) W[i] = (const float*)d_in[8 + i];

    float *acc_c, *acc_w, *acc_r, *Oc, *xp, *xa, *WhiB;
    int *cnt_c, *cnt_w, *cnt_r, *rp_c, *rp_w, *rp_r, *cur_c, *cur_w, *cur_r;
    int *col_c, *col_w, *col_r, *total;
    cudaGetSymbolAddress((void**)&acc_c, g_acc_c);
    cudaGetSymbolAddress((void**)&acc_w, g_acc_w);
    cudaGetSymbolAddress((void**)&acc_r, g_acc_r);
    cudaGetSymbolAddress((void**)&Oc, g_Oc);
    cudaGetSymbolAddress((void**)&xp, g_xp);
    cudaGetSymbolAddress((void**)&xa, g_xa);
    cudaGetSymbolAddress((void**)&WhiB, g_Whi);
    cudaGetSymbolAddress((void**)&cnt_c, g_cnt_c);
    cudaGetSymbolAddress((void**)&cnt_w, g_cnt_w);
    cudaGetSymbolAddress((void**)&cnt_r, g_cnt_r);
    cudaGetSymbolAddress((void**)&rp_c, g_rp_c);
    cudaGetSymbolAddress((void**)&rp_w, g_rp_w);
    cudaGetSymbolAddress((void**)&rp_r, g_rp_r);
    cudaGetSymbolAddress((void**)&cur_c, g_cur_c);
    cudaGetSymbolAddress((void**)&cur_w, g_cur_w);
    cudaGetSymbolAddress((void**)&cur_r, g_cur_r);
    cudaGetSymbolAddress((void**)&col_c, g_col_c);
    cudaGetSymbolAddress((void**)&col_w, g_col_w);
    cudaGetSymbolAddress((void**)&col_r, g_col_r);
    cudaGetSymbolAddress((void**)&total, g_total);

    // ---- CSR build ----
    cudaMemsetAsync(cnt_c, 0, NP * sizeof(int));
    cudaMemsetAsync(cnt_w, 0, NP * sizeof(int));
    cudaMemsetAsync(cnt_r, 0, NA * sizeof(int));
    cudaMemsetAsync(total, 0, 3 * sizeof(int));
    counti_kernel<<<(EC + 255) / 256, 256>>>(cd, cnt_c, EC);
    counti_kernel<<<(EW + 255) / 256, 256>>>(wd, cnt_w, EW);
    counti_kernel<<<(EW + 255) / 256, 256>>>(rd, cnt_r, EW);
    assign_kernel<<<(NP + 255) / 256, 256>>>(cnt_c, rp_c, cur_c, total + 0, NP);
    assign_kernel<<<(NP + 255) / 256, 256>>>(cnt_w, rp_w, cur_w, total + 1, NP);
    assign_kernel<<<(NA + 255) / 256, 256>>>(cnt_r, rp_r, cur_r, total + 2, NA);
    fill_kernel<<<(EC + 255) / 256, 256>>>(cs, cd, cur_c, col_c, EC);
    fill_kernel<<<(EW + 255) / 256, 256>>>(ws, wd, cur_w, col_w, EW);
    fill_kernel<<<(EW + 255) / 256, 256>>>(rs, rd, cur_r, col_r, EW);

    // ---- weight prep (tf32 round once) ----
    for (int l = 0; l < 2; l++)
        for (int t = 0; t < 3; t++) {
            const float* Wl = W[l * 9 + t * 3 + 0];
            const float* Wr = W[l * 9 + t * 3 + 2];
            prep_hi<<<128, 256>>>(Wl, Wr, WhiB + (l * 3 + t) * 256 * 128);
        }

    const float* xpl = x_paper;
    const float* xal = x_author;
    for (int l = 0; l < 2; l++) {
        aggregate_kernel<<<(NP * 32 + 255) / 256, 256>>>(xpl, rp_c, cnt_c, col_c, acc_c, NP);
        aggregate_kernel<<<(NP * 32 + 255) / 256, 256>>>(xal, rp_w, cnt_w, col_w, acc_w, NP);
        aggregate_kernel<<<(NA * 32 + 255) / 256, 256>>>(xpl, rp_r, cnt_r, col_r, acc_r, NA);

        const float* Whc = WhiB + (l * 3 + 0) * 256 * 128;
        const float* Whw = WhiB + (l * 3 + 1) * 256 * 128;
        const float* Whr = WhiB + (l * 3 + 2) * 256 * 128;

        float* po = (l == 1) ? (float*)d_out : xp;
        float* ao = (l == 1) ? ((float*)d_out + (size_t)NP * H) : xa;

        sage_gemm_tc<0><<<(NP + 127) / 128, 256>>>(
            acc_c, xpl, Whc, W[l * 9 + 1], nullptr, Oc, NP);
        sage_gemm_tc<1><<<(NP + 127) / 128, 256>>>(
            acc_w, xpl, Whw, W[l * 9 + 4], Oc, po, NP);
        sage_gemm_tc<2><<<(NA + 127) / 128, 256>>>(
            acc_r, xal, Whr, W[l * 9 + 7], nullptr, ao, NA);

        xpl = xp;
        xal = xa;
    }
    (void)n_in; (void)out_size; (void)x_author;
}

// round 14
// speedup vs baseline: 2.0147x; 1.0846x over previous
#include <cuda_runtime.h>
#include <cstdint>

#define NP 100000
#define NA 50000
#define H  128
#define EC_MAX 1000000
#define EW_MAX 320000

// ---------------- device scratch ----------------
__device__ float g_acc_c[(size_t)NP * H];
__device__ float g_acc_w[(size_t)NP * H];
__device__ float g_acc_r[(size_t)NA * H];
__device__ float g_Oc[(size_t)NP * H];      // cites: 0.5 * O / ||O||
__device__ float g_xp[(size_t)NP * H];
__device__ float g_xa[(size_t)NA * H];
__device__ float g_Whi[6][256 * 128];       // [k][n] tf32-rounded weights
// CSR
__device__ int g_cnt_c[NP], g_cnt_w[NP], g_cnt_r[NA];
__device__ int g_rp_c[NP], g_rp_w[NP], g_rp_r[NA];
__device__ int g_cur_c[NP], g_cur_w[NP], g_cur_r[NA];
__device__ int g_col_c[EC_MAX], g_col_w[EW_MAX], g_col_r[EW_MAX];
__device__ int g_total[3];

// ---------------- helpers ----------------
__device__ __forceinline__ uint32_t f2tf_u(float f) {
    uint32_t r;
    asm("cvt.rna.tf32.f32 %0, %1;" : "=r"(r) : "f"(f));
    return r;
}
__device__ __forceinline__ float f2tf_f(float f) { return __uint_as_float(f2tf_u(f)); }

// ---------------- CSR build ----------------
__global__ void counti_kernel(const int* __restrict__ dst, int* __restrict__ cnt, int nE) {
    int e = blockIdx.x * blockDim.x + threadIdx.x;
    if (e < nE) atomicAdd(&cnt[dst[e]], 1);
}

__global__ void assign_kernel(const int* __restrict__ cnt, int* __restrict__ rp,
                              int* __restrict__ cur, int* __restrict__ total, int n) {
    int i = blockIdx.x * blockDim.x + threadIdx.x;
    int lane = threadIdx.x & 31;
    int v = (i < n) ? cnt[i] : 0;
    int incl = v;
#pragma unroll
    for (int o = 1; o < 32; o <<= 1) {
        int t = __shfl_up_sync(0xffffffffu, incl, o);
        if (lane >= o) incl += t;
    }
    int wsum = __shfl_sync(0xffffffffu, incl, 31);
    int base = 0;
    if (lane == 31) base = atomicAdd(total, wsum);
    base = __shfl_sync(0xffffffffu, base, 31);
    int off = base + incl - v;
    if (i < n) { rp[i] = off; cur[i] = off; }
}

__global__ void fill_kernel(const int* __restrict__ src, const int* __restrict__ dst,
                            int* __restrict__ cur, int* __restrict__ col, int nE) {
    int e = blockIdx.x * blockDim.x + threadIdx.x;
    if (e < nE) {
        int d = dst[e];
        int p = atomicAdd(&cur[d], 1);
        col[p] = src[e];
    }
}

// ---------------- gather-mean aggregation: warp per dst node ----------------
__global__ void aggregate_kernel(const float* __restrict__ x, const int* __restrict__ rp,
                                 const int* __restrict__ cnt, const int* __restrict__ col,
                                 float* __restrict__ acc, int n) {
    int gw   = (blockIdx.x * blockDim.x + threadIdx.x) >> 5;
    int lane = threadIdx.x & 31;
    if (gw >= n) return;
    const int beg = __ldg(&rp[gw]);
    const int deg = __ldg(&cnt[gw]);
    const int end = beg + deg;
    float4 s = make_float4(0.f, 0.f, 0.f, 0.f);
    for (int b = beg; b < end; b += 32) {
        int nb = min(32, end - b);
        int my = (b + lane < end) ? __ldg(&col[b + lane]) : 0;
        for (int j = 0; j < nb; j++) {
            int sn = __shfl_sync(0xffffffffu, my, j);
            float4 v = *(const float4*)(x + (size_t)sn * H + lane * 4);
            s.x += v.x; s.y += v.y; s.z += v.z; s.w += v.w;
        }
    }
    float inv = 1.0f / fmaxf((float)deg, 1.0f);
    s.x *= inv; s.y *= inv; s.z *= inv; s.w *= inv;
    *(float4*)(acc + (size_t)gw * H + lane * 4) = s;
}

// ---------------- weight prep: tf32-round W = [Wl; Wr] into [k][n] ----------------
__global__ void prep_hi(const float* __restrict__ Wl, const float* __restrict__ Wr,
                        float* __restrict__ hi) {
    int i = blockIdx.x * blockDim.x + threadIdx.x;
    if (i < 256 * 128) {
        int k = i >> 7, nn = i & 127;
        float w = (k < 128) ? Wl[k * 128 + nn] : Wr[(k - 128) * 128 + nn];
        hi[i] = f2tf_f(w);
    }
}

// ---------------- single-pass tf32 GEMM + A reg prefetch + fused normalize ----------------
// MODE 0: out = O*0.5/||O||              (cites -> Oc buffer)
// MODE 1: out = relu(prev + O*0.5/||O||) (writes -> paper out)
// MODE 2: out = relu(O/||O||)            (rev -> author out)
#define AS_STRIDE 36
#define BS_STRIDE 132

template <int MODE>
__global__ void __launch_bounds__(256, 2) sage_gemm_tc(
    const float* __restrict__ acc, const float* __restrict__ xdst,
    const float* __restrict__ Whi, const float* __restrict__ bias,
    const float* __restrict__ prev, float* __restrict__ O, int n)
{
    __shared__ float bs[128];
    __shared__ float As[128 * AS_STRIDE];
    __shared__ float Bh[32 * BS_STRIDE];
    __shared__ float rowsq[256];

    const int tid  = threadIdx.x;
    const int lane = tid & 31;
    const int wid  = tid >> 5;
    const int wm   = wid & 3;
    const int wn   = wid >> 2;
    const int row0 = blockIdx.x * 128;
    const int rq   = lane >> 2;
    const int cq   = lane & 3;

    if (tid < 128) bs[tid] = __ldg(&bias[tid]);
    __syncthreads();

    float c[2][8][4];
#pragma unroll
    for (int mt = 0; mt < 2; mt++)
#pragma unroll
        for (int nt = 0; nt < 8; nt++) {
            float b0 = bs[wn * 64 + nt * 8 + cq * 2];
            float b1 = bs[wn * 64 + nt * 8 + cq * 2 + 1];
            c[mt][nt][0] = b0; c[mt][nt][1] = b1;
            c[mt][nt][2] = b0; c[mt][nt][3] = b1;
        }

    // prefetch chunk 0's A tile into registers
    float4 areg[4];
#pragma unroll
    for (int l = 0; l < 4; l++) {
        int idx = tid + l * 256;
        int r   = idx >> 3;
        int klv = (idx & 7) << 2;
        int rg  = row0 + r;
        areg[l] = make_float4(0.f, 0.f, 0.f, 0.f);
        if (rg < n)
            areg[l] = *(const float4*)(acc + (size_t)rg * H + klv);
    }

    for (int ch = 0; ch < 8; ch++) {
        __syncthreads();
        // store prefetched A (convert to tf32)
#pragma unroll
        for (int l = 0; l < 4; l++) {
            int idx = tid + l * 256;
            int r   = idx >> 3;
            int klv = (idx & 7) << 2;
            float* p = As + r * AS_STRIDE + klv;
            p[0] = f2tf_f(areg[l].x); p[1] = f2tf_f(areg[l].y);
            p[2] = f2tf_f(areg[l].z); p[3] = f2tf_f(areg[l].w);
        }
        // B tile [32 k][128 n], pad 132 (already tf32)
        {
            const int kc = ch * 32;
#pragma unroll
            for (int l = 0; l < 4; l++) {
                int idx = tid + l * 256;
                int k   = idx >> 5;
                int nv  = (idx & 31) << 2;
                float4 v = *(const float4*)(Whi + (size_t)(kc + k) * 128 + nv);
                *(float4*)(Bh + k * BS_STRIDE + nv) = v;
            }
        }
        // prefetch next chunk's A
        if (ch < 7) {
            const int kc = (ch + 1) * 32;
#pragma unroll
            for (int l = 0; l < 4; l++) {
                int idx = tid + l * 256;
                int r   = idx >> 3;
                int klv = (idx & 7) << 2;
                int rg  = row0 + r;
                int kg  = kc + klv;
                areg[l] = make_float4(0.f, 0.f, 0.f, 0.f);
                if (rg < n) {
                    areg[l] = (kg < 128)
                        ? *(const float4*)(acc + (size_t)rg * H + kg)
                        : *(const float4*)(xdst + (size_t)rg * H + (kg - 128));
                }
            }
        }
        __syncthreads();

        // compute: 4 ksteps of 8
#pragma unroll
        for (int ks = 0; ks < 4; ks++) {
            const int k0 = ks * 8;
            uint32_t au[2][4];
#pragma unroll
            for (int mt = 0; mt < 2; mt++) {
                const float* ap = As + (wm * 32 + mt * 16 + rq) * AS_STRIDE + k0 + cq;
                au[mt][0] = __float_as_uint(ap[0]);
                au[mt][1] = __float_as_uint(ap[8 * AS_STRIDE]);
                au[mt][2] = __float_as_uint(ap[4]);
                au[mt][3] = __float_as_uint(ap[8 * AS_STRIDE + 4]);
            }
#pragma unroll
            for (int nt = 0; nt < 8; nt++) {
                const float* bp = Bh + (k0 + cq) * BS_STRIDE + wn * 64 + nt * 8 + rq;
                uint32_t b0 = __float_as_uint(bp[0]);
                uint32_t b1 = __float_as_uint(bp[4 * BS_STRIDE]);
#pragma unroll
                for (int mt = 0; mt < 2; mt++) {
                    asm volatile(
                        "mma.sync.aligned.m16n8k8.row.col.f32.tf32.tf32.f32 "
                        "{%0, %1, %2, %3}, {%4, %5, %6, %7}, {%8, %9}, {%0, %1, %2, %3};"
                        : "+f"(c[mt][nt][0]), "+f"(c[mt][nt][1]),
                          "+f"(c[mt][nt][2]), "+f"(c[mt][nt][3])
                        : "r"(au[mt][0]), "r"(au[mt][1]), "r"(au[mt][2]), "r"(au[mt][3]),
                          "r"(b0), "r"(b1));
                }
            }
        }
    }

    // ---- fused epilogue: per-row L2 norm across both wn halves, scale/combine ----
    __syncthreads();
#pragma unroll
    for (int mt = 0; mt < 2; mt++)
#pragma unroll
        for (int hm = 0; hm < 2; hm++) {
            float s = 0.f;
#pragma unroll
            for (int nt = 0; nt < 8; nt++) {
                float a = c[mt][nt][hm * 2], b = c[mt][nt][hm * 2 + 1];
                s += a * a + b * b;
            }
            s += __shfl_xor_sync(0xffffffffu, s, 1);
            s += __shfl_xor_sync(0xffffffffu, s, 2);
            if (cq == 0) rowsq[wn * 128 + wm * 32 + mt * 16 + hm * 8 + rq] = s;
        }
    __syncthreads();

    const float SC = (MODE == 2) ? 1.0f : 0.5f;
#pragma unroll
    for (int mt = 0; mt < 2; mt++)
#pragma unroll
        for (int hm = 0; hm < 2; hm++) {
            int rl = wm * 32 + mt * 16 + hm * 8 + rq;
            int rg = row0 + rl;
            float tot = rowsq[rl] + rowsq[128 + rl];
            float f = SC / fmaxf(sqrtf(tot), 1e-12f);
            if (rg < n) {
#pragma unroll
                for (int nt = 0; nt < 8; nt++) {
                    int col = wn * 64 + nt * 8 + cq * 2;
                    float v0 = c[mt][nt][hm * 2] * f;
                    float v1 = c[mt][nt][hm * 2 + 1] * f;
                    if (MODE == 1) {
                        float2 p = *(const float2*)(prev + (size_t)rg * H + col);
                        v0 = fmaxf(p.x + v0, 0.f);
                        v1 = fmaxf(p.y + v1, 0.f);
                    } else if (MODE == 2) {
                        v0 = fmaxf(v0, 0.f);
                        v1 = fmaxf(v1, 0.f);
                    }
                    *(float2*)(O + (size_t)rg * H + col) = make_float2(v0, v1);
                }
            }
        }
}

// ---------------- host launcher ----------------
extern "C" void kernel_launch(void* const* d_in, const int* in_sizes, int n_in,
                              void* d_out, int out_size) {
    const float* x_paper  = (const float*)d_in[0];
    const float* x_author = (const float*)d_in[1];
    const int* cs = (const int*)d_in[2];
    const int* cd = (const int*)d_in[3];
    const int* ws = (const int*)d_in[4];
    const int* wd = (const int*)d_in[5];
    const int* rs = (const int*)d_in[6];
    const int* rd = (const int*)d_in[7];
    const int EC = in_sizes[2];
    const int EW = in_sizes[4];
    const float* W[18];
    for (int i = 0; i < 18; i++) W[i] = (const float*)d_in[8 + i];

    float *acc_c, *acc_w, *acc_r, *Oc, *xp, *xa, *WhiB;
    int *cnt_c, *cnt_w, *cnt_r, *rp_c, *rp_w, *rp_r, *cur_c, *cur_w, *cur_r;
    int *col_c, *col_w, *col_r, *total;
    cudaGetSymbolAddress((void**)&acc_c, g_acc_c);
    cudaGetSymbolAddress((void**)&acc_w, g_acc_w);
    cudaGetSymbolAddress((void**)&acc_r, g_acc_r);
    cudaGetSymbolAddress((void**)&Oc, g_Oc);
    cudaGetSymbolAddress((void**)&xp, g_xp);
    cudaGetSymbolAddress((void**)&xa, g_xa);
    cudaGetSymbolAddress((void**)&WhiB, g_Whi);
    cudaGetSymbolAddress((void**)&cnt_c, g_cnt_c);
    cudaGetSymbolAddress((void**)&cnt_w, g_cnt_w);
    cudaGetSymbolAddress((void**)&cnt_r, g_cnt_r);
    cudaGetSymbolAddress((void**)&rp_c, g_rp_c);
    cudaGetSymbolAddress((void**)&rp_w, g_rp_w);
    cudaGetSymbolAddress((void**)&rp_r, g_rp_r);
    cudaGetSymbolAddress((void**)&cur_c, g_cur_c);
    cudaGetSymbolAddress((void**)&cur_w, g_cur_w);
    cudaGetSymbolAddress((void**)&cur_r, g_cur_r);
    cudaGetSymbolAddress((void**)&col_c, g_col_c);
    cudaGetSymbolAddress((void**)&col_w, g_col_w);
    cudaGetSymbolAddress((void**)&col_r, g_col_r);
    cudaGetSymbolAddress((void**)&total, g_total);

    // one-time side stream + events (host resources only; created outside capture
    // on the first (correctness) call, reused identically every call)
    static cudaStream_t s2 = nullptr;
    static cudaEvent_t evF = nullptr, evD[2], evS[2];
    if (!s2) {
        cudaStreamCreateWithFlags(&s2, cudaStreamNonBlocking);
        cudaEventCreateWithFlags(&evF, cudaEventDisableTiming);
        for (int i = 0; i < 2; i++) {
            cudaEventCreateWithFlags(&evD[i], cudaEventDisableTiming);
            cudaEventCreateWithFlags(&evS[i], cudaEventDisableTiming);
        }
    }

    // ---- CSR build (default stream) ----
    cudaMemsetAsync(cnt_c, 0, NP * sizeof(int));
    cudaMemsetAsync(cnt_w, 0, NP * sizeof(int));
    cudaMemsetAsync(cnt_r, 0, NA * sizeof(int));
    cudaMemsetAsync(total, 0, 3 * sizeof(int));
    counti_kernel<<<(EC + 255) / 256, 256>>>(cd, cnt_c, EC);
    counti_kernel<<<(EW + 255) / 256, 256>>>(wd, cnt_w, EW);
    counti_kernel<<<(EW + 255) / 256, 256>>>(rd, cnt_r, EW);
    assign_kernel<<<(NP + 255) / 256, 256>>>(cnt_c, rp_c, cur_c, total + 0, NP);
    assign_kernel<<<(NP + 255) / 256, 256>>>(cnt_w, rp_w, cur_w, total + 1, NP);
    assign_kernel<<<(NA + 255) / 256, 256>>>(cnt_r, rp_r, cur_r, total + 2, NA);
    fill_kernel<<<(EC + 255) / 256, 256>>>(cs, cd, cur_c, col_c, EC);
    fill_kernel<<<(EW + 255) / 256, 256>>>(ws, wd, cur_w, col_w, EW);
    fill_kernel<<<(EW + 255) / 256, 256>>>(rs, rd, cur_r, col_r, EW);

    // ---- weight prep (tf32 round once) ----
    for (int l = 0; l < 2; l++)
        for (int t = 0; t < 3; t++) {
            const float* Wl = W[l * 9 + t * 3 + 0];
            const float* Wr = W[l * 9 + t * 3 + 2];
            prep_hi<<<128, 256>>>(Wl, Wr, WhiB + (l * 3 + t) * 256 * 128);
        }

    // fork side stream
    cudaEventRecord(evF, 0);
    cudaStreamWaitEvent(s2, evF, 0);

    const float* xpl = x_paper;
    const float* xal = x_author;
    for (int l = 0; l < 2; l++) {
        const float* Whc = WhiB + (l * 3 + 0) * 256 * 128;
        const float* Whw = WhiB + (l * 3 + 1) * 256 * 128;
        const float* Whr = WhiB + (l * 3 + 2) * 256 * 128;

        float* po = (l == 1) ? (float*)d_out : xp;
        float* ao = (l == 1) ? ((float*)d_out + (size_t)NP * H) : xa;

        // author chain on s2
        aggregate_kernel<<<(NA * 32 + 255) / 256, 256, 0, s2>>>(
            xpl, rp_r, cnt_r, col_r, acc_r, NA);
        sage_gemm_tc<2><<<(NA + 127) / 128, 256, 0, s2>>>(
            acc_r, xal, Whr, W[l * 9 + 7], nullptr, ao, NA);
        cudaEventRecord(evS[l], s2);

        // paper chain on default stream
        aggregate_kernel<<<(NP * 32 + 255) / 256, 256>>>(xpl, rp_c, cnt_c, col_c, acc_c, NP);
        aggregate_kernel<<<(NP * 32 + 255) / 256, 256>>>(xal, rp_w, cnt_w, col_w, acc_w, NP);
        sage_gemm_tc<0><<<(NP + 127) / 128, 256>>>(
            acc_c, xpl, Whc, W[l * 9 + 1], nullptr, Oc, NP);
        sage_gemm_tc<1><<<(NP + 127) / 128, 256>>>(
            acc_w, xpl, Whw, W[l * 9 + 4], Oc, po, NP);
        cudaEventRecord(evD[l], 0);

        // join: next layer (or exit) needs both chains done
        cudaStreamWaitEvent(0, evS[l], 0);
        cudaStreamWaitEvent(s2, evD[l], 0);

        xpl = xp;
        xal = xa;
    }
    (void)n_in; (void)out_size; (void)x_author;
}

// round 15
// speedup vs baseline: 2.1584x; 1.0714x over previous
#include <cuda_runtime.h>
#include <cstdint>

#define NP 100000
#define NA 50000
#define H  128
#define EC_MAX 1000000
#define EW_MAX 320000

// ---------------- device scratch ----------------
__device__ float g_acc_c[(size_t)NP * H];
__device__ float g_acc_w[(size_t)NP * H];
__device__ float g_acc_r[(size_t)NA * H];
__device__ float g_Oc[(size_t)NP * H];      // cites: 0.5 * O / ||O||
__device__ float g_xp[(size_t)NP * H];
__device__ float g_xa[(size_t)NA * H];
__device__ float g_Whi[6][256 * 128];       // [k][n] tf32-rounded weights
// CSR
__device__ int g_cnt_c[NP], g_cnt_w[NP], g_cnt_r[NA];
__device__ int g_rp_c[NP], g_rp_w[NP], g_rp_r[NA];
__device__ int g_cur_c[NP], g_cur_w[NP], g_cur_r[NA];
__device__ int g_col_c[EC_MAX], g_col_w[EW_MAX], g_col_r[EW_MAX];
__device__ int g_total[3];

// ---------------- helpers ----------------
__device__ __forceinline__ uint32_t f2tf_u(float f) {
    uint32_t r;
    asm("cvt.rna.tf32.f32 %0, %1;" : "=r"(r) : "f"(f));
    return r;
}
__device__ __forceinline__ float f2tf_f(float f) { return __uint_as_float(f2tf_u(f)); }

// ---------------- CSR build ----------------
__global__ void counti_kernel(const int* __restrict__ dst, int* __restrict__ cnt, int nE) {
    int e = blockIdx.x * blockDim.x + threadIdx.x;
    if (e < nE) atomicAdd(&cnt[dst[e]], 1);
}

__global__ void assign_kernel(const int* __restrict__ cnt, int* __restrict__ rp,
                              int* __restrict__ cur, int* __restrict__ total, int n) {
    int i = blockIdx.x * blockDim.x + threadIdx.x;
    int lane = threadIdx.x & 31;
    int v = (i < n) ? cnt[i] : 0;
    int incl = v;
#pragma unroll
    for (int o = 1; o < 32; o <<= 1) {
        int t = __shfl_up_sync(0xffffffffu, incl, o);
        if (lane >= o) incl += t;
    }
    int wsum = __shfl_sync(0xffffffffu, incl, 31);
    int base = 0;
    if (lane == 31) base = atomicAdd(total, wsum);
    base = __shfl_sync(0xffffffffu, base, 31);
    int off = base + incl - v;
    if (i < n) { rp[i] = off; cur[i] = off; }
}

__global__ void fill_kernel(const int* __restrict__ src, const int* __restrict__ dst,
                            int* __restrict__ cur, int* __restrict__ col, int nE) {
    int e = blockIdx.x * blockDim.x + threadIdx.x;
    if (e < nE) {
        int d = dst[e];
        int p = atomicAdd(&cur[d], 1);
        col[p] = src[e];
    }
}

// ---------------- gather-mean aggregation: warp per dst node ----------------
__global__ void aggregate_kernel(const float* __restrict__ x, const int* __restrict__ rp,
                                 const int* __restrict__ cnt, const int* __restrict__ col,
                                 float* __restrict__ acc, int n) {
    int gw   = (blockIdx.x * blockDim.x + threadIdx.x) >> 5;
    int lane = threadIdx.x & 31;
    if (gw >= n) return;
    const int beg = __ldg(&rp[gw]);
    const int deg = __ldg(&cnt[gw]);
    const int end = beg + deg;
    float4 s = make_float4(0.f, 0.f, 0.f, 0.f);
    for (int b = beg; b < end; b += 32) {
        int nb = min(32, end - b);
        int my = (b + lane < end) ? __ldg(&col[b + lane]) : 0;
        for (int j = 0; j < nb; j++) {
            int sn = __shfl_sync(0xffffffffu, my, j);
            float4 v = *(const float4*)(x + (size_t)sn * H + lane * 4);
            s.x += v.x; s.y += v.y; s.z += v.z; s.w += v.w;
        }
    }
    float inv = 1.0f / fmaxf((float)deg, 1.0f);
    s.x *= inv; s.y *= inv; s.z *= inv; s.w *= inv;
    *(float4*)(acc + (size_t)gw * H + lane * 4) = s;
}

// ---------------- weight prep: tf32-round W = [Wl; Wr] into [k][n] ----------------
__global__ void prep_hi(const float* __restrict__ Wl, const float* __restrict__ Wr,
                        float* __restrict__ hi) {
    int i = blockIdx.x * blockDim.x + threadIdx.x;
    if (i < 256 * 128) {
        int k = i >> 7, nn = i & 127;
        float w = (k < 128) ? Wl[k * 128 + nn] : Wr[(k - 128) * 128 + nn];
        hi[i] = f2tf_f(w);
    }
}

// ---------------- single-pass tf32 GEMM + A reg prefetch + fused normalize ----------------
// MODE 0: out = O*0.5/||O||              (cites -> Oc buffer)
// MODE 1: out = relu(prev + O*0.5/||O||) (writes -> paper out)
// MODE 2: out = relu(O/||O||)            (rev -> author out)
#define AS_STRIDE 36
#define BS_STRIDE 132

template <int MODE>
__global__ void __launch_bounds__(256, 2) sage_gemm_tc(
    const float* __restrict__ acc, const float* __restrict__ xdst,
    const float* __restrict__ Whi, const float* __restrict__ bias,
    const float* __restrict__ prev, float* __restrict__ O, int n)
{
    __shared__ float bs[128];
    __shared__ float As[128 * AS_STRIDE];
    __shared__ float Bh[32 * BS_STRIDE];
    __shared__ float rowsq[256];

    const int tid  = threadIdx.x;
    const int lane = tid & 31;
    const int wid  = tid >> 5;
    const int wm   = wid & 3;
    const int wn   = wid >> 2;
    const int row0 = blockIdx.x * 128;
    const int rq   = lane >> 2;
    const int cq   = lane & 3;

    if (tid < 128) bs[tid] = __ldg(&bias[tid]);
    __syncthreads();

    float c[2][8][4];
#pragma unroll
    for (int mt = 0; mt < 2; mt++)
#pragma unroll
        for (int nt = 0; nt < 8; nt++) {
            float b0 = bs[wn * 64 + nt * 8 + cq * 2];
            float b1 = bs[wn * 64 + nt * 8 + cq * 2 + 1];
            c[mt][nt][0] = b0; c[mt][nt][1] = b1;
            c[mt][nt][2] = b0; c[mt][nt][3] = b1;
        }

    // prefetch chunk 0's A tile into registers
    float4 areg[4];
#pragma unroll
    for (int l = 0; l < 4; l++) {
        int idx = tid + l * 256;
        int r   = idx >> 3;
        int klv = (idx & 7) << 2;
        int rg  = row0 + r;
        areg[l] = make_float4(0.f, 0.f, 0.f, 0.f);
        if (rg < n)
            areg[l] = *(const float4*)(acc + (size_t)rg * H + klv);
    }

    for (int ch = 0; ch < 8; ch++) {
        __syncthreads();
        // store prefetched A (convert to tf32)
#pragma unroll
        for (int l = 0; l < 4; l++) {
            int idx = tid + l * 256;
            int r   = idx >> 3;
            int klv = (idx & 7) << 2;
            float* p = As + r * AS_STRIDE + klv;
            p[0] = f2tf_f(areg[l].x); p[1] = f2tf_f(areg[l].y);
            p[2] = f2tf_f(areg[l].z); p[3] = f2tf_f(areg[l].w);
        }
        // B tile [32 k][128 n], pad 132 (already tf32)
        {
            const int kc = ch * 32;
#pragma unroll
            for (int l = 0; l < 4; l++) {
                int idx = tid + l * 256;
                int k   = idx >> 5;
                int nv  = (idx & 31) << 2;
                float4 v = *(const float4*)(Whi + (size_t)(kc + k) * 128 + nv);
                *(float4*)(Bh + k * BS_STRIDE + nv) = v;
            }
        }
        // prefetch next chunk's A
        if (ch < 7) {
            const int kc = (ch + 1) * 32;
#pragma unroll
            for (int l = 0; l < 4; l++) {
                int idx = tid + l * 256;
                int r   = idx >> 3;
                int klv = (idx & 7) << 2;
                int rg  = row0 + r;
                int kg  = kc + klv;
                areg[l] = make_float4(0.f, 0.f, 0.f, 0.f);
                if (rg < n) {
                    areg[l] = (kg < 128)
                        ? *(const float4*)(acc + (size_t)rg * H + kg)
                        : *(const float4*)(xdst + (size_t)rg * H + (kg - 128));
                }
            }
        }
        __syncthreads();

        // compute: 4 ksteps of 8
#pragma unroll
        for (int ks = 0; ks < 4; ks++) {
            const int k0 = ks * 8;
            uint32_t au[2][4];
#pragma unroll
            for (int mt = 0; mt < 2; mt++) {
                const float* ap = As + (wm * 32 + mt * 16 + rq) * AS_STRIDE + k0 + cq;
                au[mt][0] = __float_as_uint(ap[0]);
                au[mt][1] = __float_as_uint(ap[8 * AS_STRIDE]);
                au[mt][2] = __float_as_uint(ap[4]);
                au[mt][3] = __float_as_uint(ap[8 * AS_STRIDE + 4]);
            }
#pragma unroll
            for (int nt = 0; nt < 8; nt++) {
                const float* bp = Bh + (k0 + cq) * BS_STRIDE + wn * 64 + nt * 8 + rq;
                uint32_t b0 = __float_as_uint(bp[0]);
                uint32_t b1 = __float_as_uint(bp[4 * BS_STRIDE]);
#pragma unroll
                for (int mt = 0; mt < 2; mt++) {
                    asm volatile(
                        "mma.sync.aligned.m16n8k8.row.col.f32.tf32.tf32.f32 "
                        "{%0, %1, %2, %3}, {%4, %5, %6, %7}, {%8, %9}, {%0, %1, %2, %3};"
                        : "+f"(c[mt][nt][0]), "+f"(c[mt][nt][1]),
                          "+f"(c[mt][nt][2]), "+f"(c[mt][nt][3])
                        : "r"(au[mt][0]), "r"(au[mt][1]), "r"(au[mt][2]), "r"(au[mt][3]),
                          "r"(b0), "r"(b1));
                }
            }
        }
    }

    // ---- fused epilogue: per-row L2 norm across both wn halves, scale/combine ----
    __syncthreads();
#pragma unroll
    for (int mt = 0; mt < 2; mt++)
#pragma unroll
        for (int hm = 0; hm < 2; hm++) {
            float s = 0.f;
#pragma unroll
            for (int nt = 0; nt < 8; nt++) {
                float a = c[mt][nt][hm * 2], b = c[mt][nt][hm * 2 + 1];
                s += a * a + b * b;
            }
            s += __shfl_xor_sync(0xffffffffu, s, 1);
            s += __shfl_xor_sync(0xffffffffu, s, 2);
            if (cq == 0) rowsq[wn * 128 + wm * 32 + mt * 16 + hm * 8 + rq] = s;
        }
    __syncthreads();

    const float SC = (MODE == 2) ? 1.0f : 0.5f;
#pragma unroll
    for (int mt = 0; mt < 2; mt++)
#pragma unroll
        for (int hm = 0; hm < 2; hm++) {
            int rl = wm * 32 + mt * 16 + hm * 8 + rq;
            int rg = row0 + rl;
            float tot = rowsq[rl] + rowsq[128 + rl];
            float f = SC / fmaxf(sqrtf(tot), 1e-12f);
            if (rg < n) {
#pragma unroll
                for (int nt = 0; nt < 8; nt++) {
                    int col = wn * 64 + nt * 8 + cq * 2;
                    float v0 = c[mt][nt][hm * 2] * f;
                    float v1 = c[mt][nt][hm * 2 + 1] * f;
                    if (MODE == 1) {
                        float2 p = *(const float2*)(prev + (size_t)rg * H + col);
                        v0 = fmaxf(p.x + v0, 0.f);
                        v1 = fmaxf(p.y + v1, 0.f);
                    } else if (MODE == 2) {
                        v0 = fmaxf(v0, 0.f);
                        v1 = fmaxf(v1, 0.f);
                    }
                    *(float2*)(O + (size_t)rg * H + col) = make_float2(v0, v1);
                }
            }
        }
}

// ---------------- host launcher ----------------
extern "C" void kernel_launch(void* const* d_in, const int* in_sizes, int n_in,
                              void* d_out, int out_size) {
    const float* x_paper  = (const float*)d_in[0];
    const float* x_author = (const float*)d_in[1];
    const int* cs = (const int*)d_in[2];
    const int* cd = (const int*)d_in[3];
    const int* ws = (const int*)d_in[4];
    const int* wd = (const int*)d_in[5];
    const int* rs = (const int*)d_in[6];
    const int* rd = (const int*)d_in[7];
    const int EC = in_sizes[2];
    const int EW = in_sizes[4];
    const float* W[18];
    for (int i = 0; i < 18; i++) W[i] = (const float*)d_in[8 + i];

    float *acc_c, *acc_w, *acc_r, *Oc, *xp, *xa, *WhiB;
    int *cnt_c, *cnt_w, *cnt_r, *rp_c, *rp_w, *rp_r, *cur_c, *cur_w, *cur_r;
    int *col_c, *col_w, *col_r, *total;
    cudaGetSymbolAddress((void**)&acc_c, g_acc_c);
    cudaGetSymbolAddress((void**)&acc_w, g_acc_w);
    cudaGetSymbolAddress((void**)&acc_r, g_acc_r);
    cudaGetSymbolAddress((void**)&Oc, g_Oc);
    cudaGetSymbolAddress((void**)&xp, g_xp);
    cudaGetSymbolAddress((void**)&xa, g_xa);
    cudaGetSymbolAddress((void**)&WhiB, g_Whi);
    cudaGetSymbolAddress((void**)&cnt_c, g_cnt_c);
    cudaGetSymbolAddress((void**)&cnt_w, g_cnt_w);
    cudaGetSymbolAddress((void**)&cnt_r, g_cnt_r);
    cudaGetSymbolAddress((void**)&rp_c, g_rp_c);
    cudaGetSymbolAddress((void**)&rp_w, g_rp_w);
    cudaGetSymbolAddress((void**)&rp_r, g_rp_r);
    cudaGetSymbolAddress((void**)&cur_c, g_cur_c);
    cudaGetSymbolAddress((void**)&cur_w, g_cur_w);
    cudaGetSymbolAddress((void**)&cur_r, g_cur_r);
    cudaGetSymbolAddress((void**)&col_c, g_col_c);
    cudaGetSymbolAddress((void**)&col_w, g_col_w);
    cudaGetSymbolAddress((void**)&col_r, g_col_r);
    cudaGetSymbolAddress((void**)&total, g_total);

    // one-time side streams + events (host resources only)
    static cudaStream_t s2 = nullptr, s3 = nullptr, s4 = nullptr;
    static cudaEvent_t evF, evP, evW[2], evS[2], evD[2];
    if (!s2) {
        cudaStreamCreateWithFlags(&s2, cudaStreamNonBlocking);
        cudaStreamCreateWithFlags(&s3, cudaStreamNonBlocking);
        cudaStreamCreateWithFlags(&s4, cudaStreamNonBlocking);
        cudaEventCreateWithFlags(&evF, cudaEventDisableTiming);
        cudaEventCreateWithFlags(&evP, cudaEventDisableTiming);
        for (int i = 0; i < 2; i++) {
            cudaEventCreateWithFlags(&evW[i], cudaEventDisableTiming);
            cudaEventCreateWithFlags(&evS[i], cudaEventDisableTiming);
            cudaEventCreateWithFlags(&evD[i], cudaEventDisableTiming);
        }
    }

    // shared memset (total) before fork
    cudaMemsetAsync(total, 0, 3 * sizeof(int));
    cudaEventRecord(evF, 0);
    cudaStreamWaitEvent(s2, evF, 0);
    cudaStreamWaitEvent(s3, evF, 0);
    cudaStreamWaitEvent(s4, evF, 0);

    // ---- weight prep on s4 ----
    for (int l = 0; l < 2; l++)
        for (int t = 0; t < 3; t++) {
            const float* Wl = W[l * 9 + t * 3 + 0];
            const float* Wr = W[l * 9 + t * 3 + 2];
            prep_hi<<<128, 256, 0, s4>>>(Wl, Wr, WhiB + (l * 3 + t) * 256 * 128);
        }
    cudaEventRecord(evP, s4);

    // ---- CSR chains: cites on default, writes on s2, rev on s3 ----
    cudaMemsetAsync(cnt_c, 0, NP * sizeof(int), 0);
    counti_kernel<<<(EC + 255) / 256, 256>>>(cd, cnt_c, EC);
    assign_kernel<<<(NP + 255) / 256, 256>>>(cnt_c, rp_c, cur_c, total + 0, NP);
    fill_kernel<<<(EC + 255) / 256, 256>>>(cs, cd, cur_c, col_c, EC);

    cudaMemsetAsync(cnt_w, 0, NP * sizeof(int), s2);
    counti_kernel<<<(EW + 255) / 256, 256, 0, s2>>>(wd, cnt_w, EW);
    assign_kernel<<<(NP + 255) / 256, 256, 0, s2>>>(cnt_w, rp_w, cur_w, total + 1, NP);
    fill_kernel<<<(EW + 255) / 256, 256, 0, s2>>>(ws, wd, cur_w, col_w, EW);

    cudaMemsetAsync(cnt_r, 0, NA * sizeof(int), s3);
    counti_kernel<<<(EW + 255) / 256, 256, 0, s3>>>(rd, cnt_r, EW);
    assign_kernel<<<(NA + 255) / 256, 256, 0, s3>>>(cnt_r, rp_r, cur_r, total + 2, NA);
    fill_kernel<<<(EW + 255) / 256, 256, 0, s3>>>(rs, rd, cur_r, col_r, EW);

    // GEMM streams need weights
    cudaStreamWaitEvent(0, evP, 0);
    cudaStreamWaitEvent(s3, evP, 0);

    const float* xpl = x_paper;
    const float* xal = x_author;
    for (int l = 0; l < 2; l++) {
        const float* Whc = WhiB + (l * 3 + 0) * 256 * 128;
        const float* Whw = WhiB + (l * 3 + 1) * 256 * 128;
        const float* Whr = WhiB + (l * 3 + 2) * 256 * 128;

        float* po = (l == 1) ? (float*)d_out : xp;
        float* ao = (l == 1) ? ((float*)d_out + (size_t)NP * H) : xa;

        if (l == 1) {
            // layer-1 deps: agg_w needs xa (evS0) and acc_w free after gemm<1> l0 (evD0);
            // agg_r/gemm<2> need xp (evD0)
            cudaStreamWaitEvent(s2, evS[0], 0);
            cudaStreamWaitEvent(s2, evD[0], 0);
            cudaStreamWaitEvent(s3, evD[0], 0);
        }

        // writes-aggregate on s2 (only gemm<1> needs it)
        aggregate_kernel<<<(NP * 32 + 255) / 256, 256, 0, s2>>>(
            xal, rp_w, cnt_w, col_w, acc_w, NP);
        cudaEventRecord(evW[l], s2);

        // author chain on s3
        aggregate_kernel<<<(NA * 32 + 255) / 256, 256, 0, s3>>>(
            xpl, rp_r, cnt_r, col_r, acc_r, NA);
        sage_gemm_tc<2><<<(NA + 127) / 128, 256, 0, s3>>>(
            acc_r, xal, Whr, W[l * 9 + 7], nullptr, ao, NA);
        cudaEventRecord(evS[l], s3);

        // paper chain on default
        aggregate_kernel<<<(NP * 32 + 255) / 256, 256>>>(xpl, rp_c, cnt_c, col_c, acc_c, NP);
        sage_gemm_tc<0><<<(NP + 127) / 128, 256>>>(
            acc_c, xpl, Whc, W[l * 9 + 1], nullptr, Oc, NP);
        cudaStreamWaitEvent(0, evW[l], 0);
        sage_gemm_tc<1><<<(NP + 127) / 128, 256>>>(
            acc_w, xpl, Whw, W[l * 9 + 4], Oc, po, NP);
        cudaEventRecord(evD[l], 0);

        xpl = xp;
        xal = xa;
    }
    // join all side streams into default before capture end
    cudaStreamWaitEvent(0, evS[1], 0);

    (void)n_in; (void)out_size; (void)x_author;
}

// round 17
// speedup vs baseline: 2.1587x; 1.0001x over previous
#include <cuda_runtime.h>
#include <cuda_fp16.h>
#include <cstdint>

#define NP 100000
#define NA 50000
#define H  128
#define EC_MAX 1000000
#define EW_MAX 320000

// ---------------- device scratch ----------------
__device__ float g_acc_c[(size_t)NP * H];
__device__ float g_acc_w[(size_t)NP * H];
__device__ float g_acc_r[(size_t)NA * H];
__device__ float g_Oc[(size_t)NP * H];      // cites: 0.5 * O / ||O||
__device__ __half g_xph[(size_t)NP * H];    // layer-0 paper output (fp16)
__device__ __half g_xah[(size_t)NA * H];    // layer-0 author output (fp16)
__device__ float g_Whi[6][256 * 128];       // [k][n] tf32-rounded weights
// CSR
__device__ int g_cnt_c[NP], g_cnt_w[NP], g_cnt_r[NA];
__device__ int g_rp_c[NP], g_rp_w[NP], g_rp_r[NA];
__device__ int g_cur_c[NP], g_cur_w[NP], g_cur_r[NA];
__device__ int g_col_c[EC_MAX], g_col_w[EW_MAX], g_col_r[EW_MAX];
__device__ int g_total[3];

// ---------------- helpers ----------------
__device__ __forceinline__ uint32_t f2tf_u(float f) {
    uint32_t r;
    asm("cvt.rna.tf32.f32 %0, %1;" : "=r"(r) : "f"(f));
    return r;
}
__device__ __forceinline__ float f2tf_f(float f) { return __uint_as_float(f2tf_u(f)); }

// ---------------- CSR build ----------------
__global__ void counti_kernel(const int* __restrict__ dst, int* __restrict__ cnt, int nE) {
    int e = blockIdx.x * blockDim.x + threadIdx.x;
    if (e < nE) atomicAdd(&cnt[dst[e]], 1);
}

__global__ void assign_kernel(const int* __restrict__ cnt, int* __restrict__ rp,
                              int* __restrict__ cur, int* __restrict__ total, int n) {
    int i = blockIdx.x * blockDim.x + threadIdx.x;
    int lane = threadIdx.x & 31;
    int v = (i < n) ? cnt[i] : 0;
    int incl = v;
#pragma unroll
    for (int o = 1; o < 32; o <<= 1) {
        int t = __shfl_up_sync(0xffffffffu, incl, o);
        if (lane >= o) incl += t;
    }
    int wsum = __shfl_sync(0xffffffffu, incl, 31);
    int base = 0;
    if (lane == 31) base = atomicAdd(total, wsum);
    base = __shfl_sync(0xffffffffu, base, 31);
    int off = base + incl - v;
    if (i < n) { rp[i] = off; cur[i] = off; }
}

__global__ void fill_kernel(const int* __restrict__ src, const int* __restrict__ dst,
                            int* __restrict__ cur, int* __restrict__ col, int nE) {
    int e = blockIdx.x * blockDim.x + threadIdx.x;
    if (e < nE) {
        int d = dst[e];
        int p = atomicAdd(&cur[d], 1);
        col[p] = src[e];
    }
}

// ---------------- gather-mean aggregation: warp per dst node ----------------
template <bool HALFIN>
__global__ void aggregate_kernel(const float* __restrict__ x, const __half* __restrict__ xh,
                                 const int* __restrict__ rp, const int* __restrict__ cnt,
                                 const int* __restrict__ col, float* __restrict__ acc, int n) {
    int gw   = (blockIdx.x * blockDim.x + threadIdx.x) >> 5;
    int lane = threadIdx.x & 31;
    if (gw >= n) return;
    const int beg = __ldg(&rp[gw]);
    const int deg = __ldg(&cnt[gw]);
    const int end = beg + deg;
    float4 s = make_float4(0.f, 0.f, 0.f, 0.f);
    for (int b = beg; b < end; b += 32) {
        int nb = min(32, end - b);
        int my = (b + lane < end) ? __ldg(&col[b + lane]) : 0;
        for (int j = 0; j < nb; j++) {
            int sn = __shfl_sync(0xffffffffu, my, j);
            if (HALFIN) {
                uint2 u = *(const uint2*)(xh + (size_t)sn * H + lane * 4);
                float2 f0 = __half22float2(*(__half2*)&u.x);
                float2 f1 = __half22float2(*(__half2*)&u.y);
                s.x += f0.x; s.y += f0.y; s.z += f1.x; s.w += f1.y;
            } else {
                float4 v = *(const float4*)(x + (size_t)sn * H + lane * 4);
                s.x += v.x; s.y += v.y; s.z += v.z; s.w += v.w;
            }
        }
    }
    float inv = 1.0f / fmaxf((float)deg, 1.0f);
    s.x *= inv; s.y *= inv; s.z *= inv; s.w *= inv;
    *(float4*)(acc + (size_t)gw * H + lane * 4) = s;
}

// ---------------- weight prep: tf32-round W = [Wl; Wr] into [k][n] ----------------
__global__ void prep_hi(const float* __restrict__ Wl, const float* __restrict__ Wr,
                        float* __restrict__ hi) {
    int i = blockIdx.x * blockDim.x + threadIdx.x;
    if (i < 256 * 128) {
        int k = i >> 7, nn = i & 127;
        float w = (k < 128) ? Wl[k * 128 + nn] : Wr[(k - 128) * 128 + nn];
        hi[i] = f2tf_f(w);
    }
}

// ---------------- single-pass tf32 GEMM + A reg prefetch + fused normalize ----------------
// MODE 0: out = O*0.5/||O||              (cites -> Oc buffer, fp32)
// MODE 1: out = relu(prev + O*0.5/||O||) (writes -> paper out)
// MODE 2: out = relu(O/||O||)            (rev -> author out)
// HALFX:   xdst (A-side k>=128) is fp16;  HALFOUT: result stored fp16
#define AS_STRIDE 36
#define BS_STRIDE 132

template <int MODE, bool HALFX, bool HALFOUT>
__global__ void __launch_bounds__(256, 2) sage_gemm_tc(
    const float* __restrict__ acc, const float* __restrict__ xdst,
    const __half* __restrict__ xdsth,
    const float* __restrict__ Whi, const float* __restrict__ bias,
    const float* __restrict__ prev, float* __restrict__ O,
    __half* __restrict__ Oh, int n)
{
    __shared__ float bs[128];
    __shared__ float As[128 * AS_STRIDE];
    __shared__ float Bh[32 * BS_STRIDE];
    __shared__ float rowsq[256];

    const int tid  = threadIdx.x;
    const int lane = tid & 31;
    const int wid  = tid >> 5;
    const int wm   = wid & 3;
    const int wn   = wid >> 2;
    const int row0 = blockIdx.x * 128;
    const int rq   = lane >> 2;
    const int cq   = lane & 3;

    if (tid < 128) bs[tid] = __ldg(&bias[tid]);
    __syncthreads();

    float c[2][8][4];
#pragma unroll
    for (int mt = 0; mt < 2; mt++)
#pragma unroll
        for (int nt = 0; nt < 8; nt++) {
            float b0 = bs[wn * 64 + nt * 8 + cq * 2];
            float b1 = bs[wn * 64 + nt * 8 + cq * 2 + 1];
            c[mt][nt][0] = b0; c[mt][nt][1] = b1;
            c[mt][nt][2] = b0; c[mt][nt][3] = b1;
        }

    // prefetch chunk 0's A tile into registers (always acc side)
    float4 areg[4];
#pragma unroll
    for (int l = 0; l < 4; l++) {
        int idx = tid + l * 256;
        int r   = idx >> 3;
        int klv = (idx & 7) << 2;
        int rg  = row0 + r;
        areg[l] = make_float4(0.f, 0.f, 0.f, 0.f);
        if (rg < n)
            areg[l] = *(const float4*)(acc + (size_t)rg * H + klv);
    }

    for (int ch = 0; ch < 8; ch++) {
        __syncthreads();
        // store prefetched A (convert to tf32)
#pragma unroll
        for (int l = 0; l < 4; l++) {
            int idx = tid + l * 256;
            int r   = idx >> 3;
            int klv = (idx & 7) << 2;
            float* p = As + r * AS_STRIDE + klv;
            p[0] = f2tf_f(areg[l].x); p[1] = f2tf_f(areg[l].y);
            p[2] = f2tf_f(areg[l].z); p[3] = f2tf_f(areg[l].w);
        }
        // B tile [32 k][128 n], pad 132 (already tf32)
        {
            const int kc = ch * 32;
#pragma unroll
            for (int l = 0; l < 4; l++) {
                int idx = tid + l * 256;
                int k   = idx >> 5;
                int nv  = (idx & 31) << 2;
                float4 v = *(const float4*)(Whi + (size_t)(kc + k) * 128 + nv);
                *(float4*)(Bh + k * BS_STRIDE + nv) = v;
            }
        }
        // prefetch next chunk's A
        if (ch < 7) {
            const int kc = (ch + 1) * 32;
#pragma unroll
            for (int l = 0; l < 4; l++) {
                int idx = tid + l * 256;
                int r   = idx >> 3;
                int klv = (idx & 7) << 2;
                int rg  = row0 + r;
                int kg  = kc + klv;
                areg[l] = make_float4(0.f, 0.f, 0.f, 0.f);
                if (rg < n) {
                    if (kg < 128) {
                        areg[l] = *(const float4*)(acc + (size_t)rg * H + kg);
                    } else if (HALFX) {
                        uint2 u = *(const uint2*)(xdsth + (size_t)rg * H + (kg - 128));
                        float2 f0 = __half22float2(*(__half2*)&u.x);
                        float2 f1 = __half22float2(*(__half2*)&u.y);
                        areg[l] = make_float4(f0.x, f0.y, f1.x, f1.y);
                    } else {
                        areg[l] = *(const float4*)(xdst + (size_t)rg * H + (kg - 128));
                    }
                }
            }
        }
        __syncthreads();

        // compute: 4 ksteps of 8
#pragma unroll
        for (int ks = 0; ks < 4; ks++) {
            const int k0 = ks * 8;
            uint32_t au[2][4];
#pragma unroll
            for (int mt = 0; mt < 2; mt++) {
                const float* ap = As + (wm * 32 + mt * 16 + rq) * AS_STRIDE + k0 + cq;
                au[mt][0] = __float_as_uint(ap[0]);
                au[mt][1] = __float_as_uint(ap[8 * AS_STRIDE]);
                au[mt][2] = __float_as_uint(ap[4]);
                au[mt][3] = __float_as_uint(ap[8 * AS_STRIDE + 4]);
            }
#pragma unroll
            for (int nt = 0; nt < 8; nt++) {
                const float* bp = Bh + (k0 + cq) * BS_STRIDE + wn * 64 + nt * 8 + rq;
                uint32_t b0 = __float_as_uint(bp[0]);
                uint32_t b1 = __float_as_uint(bp[4 * BS_STRIDE]);
#pragma unroll
                for (int mt = 0; mt < 2; mt++) {
                    asm volatile(
                        "mma.sync.aligned.m16n8k8.row.col.f32.tf32.tf32.f32 "
                        "{%0, %1, %2, %3}, {%4, %5, %6, %7}, {%8, %9}, {%0, %1, %2, %3};"
                        : "+f"(c[mt][nt][0]), "+f"(c[mt][nt][1]),
                          "+f"(c[mt][nt][2]), "+f"(c[mt][nt][3])
                        : "r"(au[mt][0]), "r"(au[mt][1]), "r"(au[mt][2]), "r"(au[mt][3]),
                          "r"(b0), "r"(b1));
                }
            }
        }
    }

    // ---- fused epilogue: per-row L2 norm across both wn halves, scale/combine ----
    __syncthreads();
#pragma unroll
    for (int mt = 0; mt < 2; mt++)
#pragma unroll
        for (int hm = 0; hm < 2; hm++) {
            float s = 0.f;
#pragma unroll
            for (int nt = 0; nt < 8; nt++) {
                float a = c[mt][nt][hm * 2], b = c[mt][nt][hm * 2 + 1];
                s += a * a + b * b;
            }
            s += __shfl_xor_sync(0xffffffffu, s, 1);
            s += __shfl_xor_sync(0xffffffffu, s, 2);
            if (cq == 0) rowsq[wn * 128 + wm * 32 + mt * 16 + hm * 8 + rq] = s;
        }
    __syncthreads();

    const float SC = (MODE == 2) ? 1.0f : 0.5f;
#pragma unroll
    for (int mt = 0; mt < 2; mt++)
#pragma unroll
        for (int hm = 0; hm < 2; hm++) {
            int rl = wm * 32 + mt * 16 + hm * 8 + rq;
            int rg = row0 + rl;
            float tot = rowsq[rl] + rowsq[128 + rl];
            float f = SC / fmaxf(sqrtf(tot), 1e-12f);
            if (rg < n) {
#pragma unroll
                for (int nt = 0; nt < 8; nt++) {
                    int col = wn * 64 + nt * 8 + cq * 2;
                    float v0 = c[mt][nt][hm * 2] * f;
                    float v1 = c[mt][nt][hm * 2 + 1] * f;
                    if (MODE == 1) {
                        float2 p = *(const float2*)(prev + (size_t)rg * H + col);
                        v0 = fmaxf(p.x + v0, 0.f);
                        v1 = fmaxf(p.y + v1, 0.f);
                    } else if (MODE == 2) {
                        v0 = fmaxf(v0, 0.f);
                        v1 = fmaxf(v1, 0.f);
                    }
                    if (HALFOUT) {
                        *(__half2*)(Oh + (size_t)rg * H + col) = __floats2half2_rn(v0, v1);
                    } else {
                        *(float2*)(O + (size_t)rg * H + col) = make_float2(v0, v1);
                    }
                }
            }
        }
}

// ---------------- host launcher ----------------
extern "C" void kernel_launch(void* const* d_in, const int* in_sizes, int n_in,
                              void* d_out, int out_size) {
    const float* x_paper  = (const float*)d_in[0];
    const float* x_author = (const float*)d_in[1];
    const int* cs = (const int*)d_in[2];
    const int* cd = (const int*)d_in[3];
    const int* ws = (const int*)d_in[4];
    const int* wd = (const int*)d_in[5];
    const int* rs = (const int*)d_in[6];
    const int* rd = (const int*)d_in[7];
    const int EC = in_sizes[2];
    const int EW = in_sizes[4];
    const float* W[18];
    for (int i = 0; i < 18; i++) W[i] = (const float*)d_in[8 + i];

    float *acc_c, *acc_w, *acc_r, *Oc, *WhiB;
    __half *xph, *xah;
    int *cnt_c, *cnt_w, *cnt_r, *rp_c, *rp_w, *rp_r, *cur_c, *cur_w, *cur_r;
    int *col_c, *col_w, *col_r, *total;
    cudaGetSymbolAddress((void**)&acc_c, g_acc_c);
    cudaGetSymbolAddress((void**)&acc_w, g_acc_w);
    cudaGetSymbolAddress((void**)&acc_r, g_acc_r);
    cudaGetSymbolAddress((void**)&Oc, g_Oc);
    cudaGetSymbolAddress((void**)&xph, g_xph);
    cudaGetSymbolAddress((void**)&xah, g_xah);
    cudaGetSymbolAddress((void**)&WhiB, g_Whi);
    cudaGetSymbolAddress((void**)&cnt_c, g_cnt_c);
    cudaGetSymbolAddress((void**)&cnt_w, g_cnt_w);
    cudaGetSymbolAddress((void**)&cnt_r, g_cnt_r);
    cudaGetSymbolAddress((void**)&rp_c, g_rp_c);
    cudaGetSymbolAddress((void**)&rp_w, g_rp_w);
    cudaGetSymbolAddress((void**)&rp_r, g_rp_r);
    cudaGetSymbolAddress((void**)&cur_c, g_cur_c);
    cudaGetSymbolAddress((void**)&cur_w, g_cur_w);
    cudaGetSymbolAddress((void**)&cur_r, g_cur_r);
    cudaGetSymbolAddress((void**)&col_c, g_col_c);
    cudaGetSymbolAddress((void**)&col_w, g_col_w);
    cudaGetSymbolAddress((void**)&col_r, g_col_r);
    cudaGetSymbolAddress((void**)&total, g_total);

    // one-time side streams + events (host resources only; same width as R15)
    static cudaStream_t s2 = nullptr, s3 = nullptr, s4 = nullptr;
    static cudaEvent_t evF, evP, evW[2], evS[2], evD[2];
    if (!s2) {
        cudaStreamCreateWithFlags(&s2, cudaStreamNonBlocking);
        cudaStreamCreateWithFlags(&s3, cudaStreamNonBlocking);
        cudaStreamCreateWithFlags(&s4, cudaStreamNonBlocking);
        cudaEventCreateWithFlags(&evF, cudaEventDisableTiming);
        cudaEventCreateWithFlags(&evP, cudaEventDisableTiming);
        for (int i = 0; i < 2; i++) {
            cudaEventCreateWithFlags(&evW[i], cudaEventDisableTiming);
            cudaEventCreateWithFlags(&evS[i], cudaEventDisableTiming);
            cudaEventCreateWithFlags(&evD[i], cudaEventDisableTiming);
        }
    }

    // shared memset (total) before fork
    cudaMemsetAsync(total, 0, 3 * sizeof(int));
    cudaEventRecord(evF, 0);
    cudaStreamWaitEvent(s2, evF, 0);
    cudaStreamWaitEvent(s3, evF, 0);
    cudaStreamWaitEvent(s4, evF, 0);

    // ---- weight prep on s4 ----
    for (int l = 0; l < 2; l++)
        for (int t = 0; t < 3; t++) {
            const float* Wl = W[l * 9 + t * 3 + 0];
            const float* Wr = W[l * 9 + t * 3 + 2];
            prep_hi<<<128, 256, 0, s4>>>(Wl, Wr, WhiB + (l * 3 + t) * 256 * 128);
        }
    cudaEventRecord(evP, s4);

    // ---- CSR chains: cites on default, writes on s2, rev on s3 ----
    cudaMemsetAsync(cnt_c, 0, NP * sizeof(int), 0);
    counti_kernel<<<(EC + 255) / 256, 256>>>(cd, cnt_c, EC);
    assign_kernel<<<(NP + 255) / 256, 256>>>(cnt_c, rp_c, cur_c, total + 0, NP);
    fill_kernel<<<(EC + 255) / 256, 256>>>(cs, cd, cur_c, col_c, EC);

    cudaMemsetAsync(cnt_w, 0, NP * sizeof(int), s2);
    counti_kernel<<<(EW + 255) / 256, 256, 0, s2>>>(wd, cnt_w, EW);
    assign_kernel<<<(NP + 255) / 256, 256, 0, s2>>>(cnt_w, rp_w, cur_w, total + 1, NP);
    fill_kernel<<<(EW + 255) / 256, 256, 0, s2>>>(ws, wd, cur_w, col_w, EW);

    cudaMemsetAsync(cnt_r, 0, NA * sizeof(int), s3);
    counti_kernel<<<(EW + 255) / 256, 256, 0, s3>>>(rd, cnt_r, EW);
    assign_kernel<<<(NA + 255) / 256, 256, 0, s3>>>(cnt_r, rp_r, cur_r, total + 2, NA);
    fill_kernel<<<(EW + 255) / 256, 256, 0, s3>>>(rs, rd, cur_r, col_r, EW);

    // GEMM streams need weights
    cudaStreamWaitEvent(0, evP, 0);
    cudaStreamWaitEvent(s3, evP, 0);

    for (int l = 0; l < 2; l++) {
        const float* Whc = WhiB + (l * 3 + 0) * 256 * 128;
        const float* Whw = WhiB + (l * 3 + 1) * 256 * 128;
        const float* Whr = WhiB + (l * 3 + 2) * 256 * 128;
        const float* bc = W[l * 9 + 1];
        const float* bw = W[l * 9 + 4];
        const float* br = W[l * 9 + 7];

        if (l == 1) {
            // deps: agg_w needs xa (evS0) + acc_w WAR (evD0); agg_r/gemm2 need xp (evD0)
            cudaStreamWaitEvent(s2, evS[0], 0);
            cudaStreamWaitEvent(s2, evD[0], 0);
            cudaStreamWaitEvent(s3, evD[0], 0);
        }

        if (l == 0) {
            // writes-aggregate on s2
            aggregate_kernel<false><<<(NP * 32 + 255) / 256, 256, 0, s2>>>(
                x_author, nullptr, rp_w, cnt_w, col_w, acc_w, NP);
            cudaEventRecord(evW[0], s2);
            // author chain on s3
            aggregate_kernel<false><<<(NA * 32 + 255) / 256, 256, 0, s3>>>(
                x_paper, nullptr, rp_r, cnt_r, col_r, acc_r, NA);
            sage_gemm_tc<2, false, true><<<(NA + 127) / 128, 256, 0, s3>>>(
                acc_r, x_author, nullptr, Whr, br, nullptr, nullptr, xah, NA);
            cudaEventRecord(evS[0], s3);
            // paper chain on default
            aggregate_kernel<false><<<(NP * 32 + 255) / 256, 256>>>(
                x_paper, nullptr, rp_c, cnt_c, col_c, acc_c, NP);
            sage_gemm_tc<0, false, false><<<(NP + 127) / 128, 256>>>(
                acc_c, x_paper, nullptr, Whc, bc, nullptr, Oc, nullptr, NP);
            cudaStreamWaitEvent(0, evW[0], 0);
            sage_gemm_tc<1, false, true><<<(NP + 127) / 128, 256>>>(
                acc_w, x_paper, nullptr, Whw, bw, Oc, nullptr, xph, NP);
            cudaEventRecord(evD[0], 0);
        } else {
            float* po = (float*)d_out;
            float* ao = (float*)d_out + (size_t)NP * H;
            // writes-aggregate on s2 (reads fp16 xa)
            aggregate_kernel<true><<<(NP * 32 + 255) / 256, 256, 0, s2>>>(
                nullptr, xah, rp_w, cnt_w, col_w, acc_w, NP);
            cudaEventRecord(evW[1], s2);
            // author chain on s3 (reads fp16 xp; A-side xdst = fp16 xa)
            aggregate_kernel<true><<<(NA * 32 + 255) / 256, 256, 0, s3>>>(
                nullptr, xph, rp_r, cnt_r, col_r, acc_r, NA);
            sage_gemm_tc<2, true, false><<<(NA + 127) / 128, 256, 0, s3>>>(
                acc_r, nullptr, xah, Whr, br, nullptr, ao, nullptr, NA);
            cudaEventRecord(evS[1], s3);
            // paper chain on default
            aggregate_kernel<true><<<(NP * 32 + 255) / 256, 256>>>(
                nullptr, xph, rp_c, cnt_c, col_c, acc_c, NP);
            sage_gemm_tc<0, true, false><<<(NP + 127) / 128, 256>>>(
                acc_c, nullptr, xph, Whc, bc, nullptr, Oc, nullptr, NP);
            cudaStreamWaitEvent(0, evW[1], 0);
            sage_gemm_tc<1, true, false><<<(NP + 127) / 128, 256>>>(
                acc_w, nullptr, xph, Whw, bw, Oc, po, nullptr, NP);
            cudaEventRecord(evD[1], 0);
        }
    }
    // join all side streams into default before capture end
    cudaStreamWaitEvent(0, evS[1], 0);

    (void)n_in; (void)out_size;
}